// round 8
// baseline (speedup 1.0000x reference)
#include <cuda_runtime.h>
#include <cuda_fp16.h>
#include <math.h>
#include <cstdint>

#define S_LEN 2048
#define HID   3584
#define NH    28
#define NKV   4
#define HD    128
#define REP   7
#define NHD   (NH * HD)
#define QK_SCALE 0.0883883476483184406f

// ---------------- scratch (device globals; no allocations allowed) ----------
__device__ float g_q[S_LEN * NH * HD];
__device__ float g_k[S_LEN * NKV * HD];
__device__ float g_v[S_LEN * NKV * HD];
__device__ float g_sin[S_LEN * 64];
__device__ float g_cos[S_LEN * 64];

__device__ __align__(16) __half g_x_hi[S_LEN * HID];
__device__ __align__(16) __half g_x_lo[S_LEN * HID];
__device__ __align__(16) __half g_wq_hi[HID * NH * HD];
__device__ __align__(16) __half g_wq_lo[HID * NH * HD];
__device__ __align__(16) __half g_wk_hi[HID * NKV * HD];
__device__ __align__(16) __half g_wk_lo[HID * NKV * HD];
__device__ __align__(16) __half g_wv_hi[HID * NKV * HD];
__device__ __align__(16) __half g_wv_lo[HID * NKV * HD];
__device__ __align__(16) __half g_wo_hi[NH * HD * HID];
__device__ __align__(16) __half g_wo_lo[NH * HD * HID];
__device__ __align__(16) __half g_a_hi[S_LEN * NH * HD];
// flash operands
__device__ __align__(16) __half g_qhi[S_LEN * NH * HD];
__device__ __align__(16) __half g_qlo[S_LEN * NH * HD];
__device__ __align__(16) __half g_khiT[NKV * HD * S_LEN];   // [NKV][HD][S]
__device__ __align__(16) __half g_kloT[NKV * HD * S_LEN];
__device__ __align__(16) __half g_vhi[S_LEN * NKV * HD];
__device__ __align__(16) __half g_vlo[S_LEN * NKV * HD];

// ---------------- HMMA helpers (base-target instructions only) --------------
__device__ __forceinline__ uint32_t smem_u32(const void* p) {
    uint32_t a;
    asm("{ .reg .u64 t; cvta.to.shared.u64 t, %1; cvt.u32.u64 %0, t; }"
        : "=r"(a) : "l"(p));
    return a;
}
__device__ __forceinline__ void ldsm_x4(uint32_t* r, uint32_t addr) {
    asm volatile("ldmatrix.sync.aligned.m8n8.x4.shared.b16 {%0,%1,%2,%3}, [%4];"
        : "=r"(r[0]), "=r"(r[1]), "=r"(r[2]), "=r"(r[3]) : "r"(addr));
}
__device__ __forceinline__ void ldsm_x4t(uint32_t* r, uint32_t addr) {
    asm volatile("ldmatrix.sync.aligned.m8n8.x4.trans.shared.b16 {%0,%1,%2,%3}, [%4];"
        : "=r"(r[0]), "=r"(r[1]), "=r"(r[2]), "=r"(r[3]) : "r"(addr));
}
__device__ __forceinline__ void mma16816(float* d, const uint32_t* a,
                                         uint32_t b0, uint32_t b1) {
    asm volatile(
        "mma.sync.aligned.m16n8k16.row.col.f32.f16.f16.f32 "
        "{%0,%1,%2,%3}, {%4,%5,%6,%7}, {%8,%9}, {%0,%1,%2,%3};"
        : "+f"(d[0]), "+f"(d[1]), "+f"(d[2]), "+f"(d[3])
        : "r"(a[0]), "r"(a[1]), "r"(a[2]), "r"(a[3]), "r"(b0), "r"(b1));
}
#define CPASYNC16(dst, src) \
    asm volatile("cp.async.cg.shared.global [%0], [%1], 16;" \
                 :: "r"(dst), "l"(src) : "memory")
#define CP_COMMIT() asm volatile("cp.async.commit_group;" ::: "memory")
#define CP_WAIT1()  asm volatile("cp.async.wait_group 1;" ::: "memory")
#define CP_WAIT0()  asm volatile("cp.async.wait_group 0;" ::: "memory")

__device__ __forceinline__ void split2(float x, float y, uint32_t& hi, uint32_t& lo) {
    __half hx = __float2half_rn(x), hy = __float2half_rn(y);
    __half lx = __float2half_rn(x - __half2float(hx));
    __half ly = __float2half_rn(y - __half2float(hy));
    hi = (uint32_t)__half_as_ushort(hx) | ((uint32_t)__half_as_ushort(hy) << 16);
    lo = (uint32_t)__half_as_ushort(lx) | ((uint32_t)__half_as_ushort(ly) << 16);
}

__device__ __forceinline__ void split4_at(const float* __restrict__ src,
                                          __half* __restrict__ hi,
                                          __half* __restrict__ lo, int i) {
    float4 v = ((const float4*)src)[i];
    __half h0 = __float2half_rn(v.x), h1 = __float2half_rn(v.y);
    __half h2 = __float2half_rn(v.z), h3 = __float2half_rn(v.w);
    __half l0 = __float2half_rn(v.x - __half2float(h0));
    __half l1 = __float2half_rn(v.y - __half2float(h1));
    __half l2 = __float2half_rn(v.z - __half2float(h2));
    __half l3 = __float2half_rn(v.w - __half2float(h3));
    ((uint2*)hi)[i] = make_uint2(
        (uint32_t)__half_as_ushort(h0) | ((uint32_t)__half_as_ushort(h1) << 16),
        (uint32_t)__half_as_ushort(h2) | ((uint32_t)__half_as_ushort(h3) << 16));
    ((uint2*)lo)[i] = make_uint2(
        (uint32_t)__half_as_ushort(l0) | ((uint32_t)__half_as_ushort(l1) << 16),
        (uint32_t)__half_as_ushort(l2) | ((uint32_t)__half_as_ushort(l3) << 16));
}

// ---------------- fused split of x + all four weights ------------------------
__global__ void split_all_kernel(const float* __restrict__ x,
                                 const float* __restrict__ wq,
                                 const float* __restrict__ wk,
                                 const float* __restrict__ wv,
                                 const float* __restrict__ wo,
                                 __half* xh, __half* xl, __half* qh, __half* ql,
                                 __half* kh, __half* kl, __half* vh, __half* vl,
                                 __half* oh, __half* ol) {
    const int C0 = S_LEN * HID / 4;
    const int C1 = C0 + HID * NH * HD / 4;
    const int C2 = C1 + HID * NKV * HD / 4;
    const int C3 = C2 + HID * NKV * HD / 4;
    const int C4 = C3 + NH * HD * HID / 4;
    int i = blockIdx.x * blockDim.x + threadIdx.x;
    if (i >= C4) return;
    if (i < C0)      split4_at(x,  xh, xl, i);
    else if (i < C1) split4_at(wq, qh, ql, i - C0);
    else if (i < C2) split4_at(wk, kh, kl, i - C1);
    else if (i < C3) split4_at(wv, vh, vl, i - C2);
    else             split4_at(wo, oh, ol, i - C3);
}

// ---------------- RoPE sin/cos table -----------------------------------------
__global__ void build_rope_kernel(const int* __restrict__ pos) {
    int idx = blockIdx.x * blockDim.x + threadIdx.x;
    if (idx >= S_LEN * 64) return;
    int i = idx & 63;
    int s = idx >> 6;
    double inv = exp(-((double)i / 64.0) * log(1.0e6));
    double ang = (double)pos[s] * inv;
    g_sin[idx] = (float)sin(ang);
    g_cos[idx] = (float)cos(ang);
}

// ---------------- fused: RoPE+split Q | RoPE+split K^T | split V -------------
__global__ void prep_attention_kernel(const float* __restrict__ Q,
                                      const float* __restrict__ Kc,
                                      const float* __restrict__ V,
                                      __half* __restrict__ qhi, __half* __restrict__ qlo,
                                      __half* __restrict__ khiT, __half* __restrict__ kloT,
                                      __half* __restrict__ vhi, __half* __restrict__ vlo) {
    const int R0 = S_LEN * NH * 64;
    const int R1 = R0 + S_LEN * NKV * 64;
    const int R2 = R1 + S_LEN * NKV * HD / 4;
    int idx = blockIdx.x * blockDim.x + threadIdx.x;
    if (idx >= R2) return;

    if (idx < R0) {
        int i = idx & 63;
        int t = idx >> 6;
        int h = t % NH;
        int s = t / NH;
        float sn = g_sin[s * 64 + i], cs = g_cos[s * 64 + i];
        const float* p = Q + ((size_t)s * NH + h) * HD;
        float x0 = p[i], x1 = p[i + 64];
        float y0 = (x0 * cs - x1 * sn) * QK_SCALE;
        float y1 = (x1 * cs + x0 * sn) * QK_SCALE;
        size_t o = ((size_t)s * NH + h) * HD;
        __half h0 = __float2half_rn(y0);
        qhi[o + i] = h0;
        qlo[o + i] = __float2half_rn(y0 - __half2float(h0));
        __half h1 = __float2half_rn(y1);
        qhi[o + i + 64] = h1;
        qlo[o + i + 64] = __float2half_rn(y1 - __half2float(h1));
    } else if (idx < R1) {
        int j = idx - R0;
        int s = j & (S_LEN - 1);
        int t = j >> 11;
        int i = t & 63;
        int kvh = t >> 6;
        float sn = g_sin[s * 64 + i], cs = g_cos[s * 64 + i];
        const float* p = Kc + ((size_t)s * NKV + kvh) * HD;
        float x0 = p[i], x1 = p[i + 64];
        float y0 = x0 * cs - x1 * sn;
        float y1 = x1 * cs + x0 * sn;
        size_t o0 = ((size_t)kvh * HD + i) * S_LEN + s;
        size_t o1 = ((size_t)kvh * HD + i + 64) * S_LEN + s;
        __half h0 = __float2half_rn(y0);
        khiT[o0] = h0;
        kloT[o0] = __float2half_rn(y0 - __half2float(h0));
        __half h1 = __float2half_rn(y1);
        khiT[o1] = h1;
        kloT[o1] = __float2half_rn(y1 - __half2float(h1));
    } else {
        split4_at(V, vhi, vlo, idx - R1);
    }
}

// ---------------- HMMA GEMM: CTA tile 128x256, warp tile 64x64 ---------------
// BK=32, 8 warps (2M x 4N). 3-stage cp.async pipeline, one sync per chunk.
// Stage 48KB: A_hi[0,8K) A_lo[8K,16K) B_hi[16K,32K) B_lo[32K,48K).
// B smem rows: 32 k-rows x 512B, 16B chunks XOR-swizzled with (k&7).
// ALO=1: 3-term; ALO=0: 2-term (A residual dropped).
template <int FUSED, int ALO>
__global__ __launch_bounds__(256)
void gemm_hmma_kernel(const __half* __restrict__ Ahi, const __half* __restrict__ Alo,
                      const __half* __restrict__ Bhi0, const __half* __restrict__ Blo0,
                      const __half* __restrict__ Bhi1, const __half* __restrict__ Blo1,
                      const __half* __restrict__ Bhi2, const __half* __restrict__ Blo2,
                      float* __restrict__ C0, float* __restrict__ C1,
                      float* __restrict__ C2, int K, int N0) {
    extern __shared__ char smem[];
    uint32_t sb = smem_u32(smem);

    int tid = threadIdx.x, wid = tid >> 5, lane = tid & 31;
    int bn = blockIdx.x, bm = blockIdx.y;
    int wm = wid & 1, wn = wid >> 1;

    const __half* Bhi = Bhi0;
    const __half* Blo = Blo0;
    float* C = C0;
    int ldn = N0, bcol = bn * 256;
    if (FUSED) {
        if (bn >= 14 && bn < 16) {
            Bhi = Bhi1; Blo = Blo1; C = C1; ldn = NKV * HD; bcol = (bn - 14) * 256;
        } else if (bn >= 16) {
            Bhi = Bhi2; Blo = Blo2; C = C2; ldn = NKV * HD; bcol = (bn - 16) * 256;
        }
    }

    // A loader: 512 16B-chunks per array, 2 per thread
    int ar0 = tid >> 2, ac0 = tid & 3;
    int ar1 = (tid + 256) >> 2, ac1 = tid & 3;
    uint32_t a_d0 = (uint32_t)(ar0 * 64 + ((ac0 ^ ((ar0 >> 1) & 3)) << 4));
    uint32_t a_d1 = (uint32_t)(ar1 * 64 + ((ac1 ^ ((ar1 >> 1) & 3)) << 4));
    // B loader: 1024 16B-chunks per array (32 k x 32 chunks), 4 per thread
    uint32_t b_d[4];
    int b_k[4], b_c[4];
#pragma unroll
    for (int j = 0; j < 4; j++) {
        int idx = tid + j * 256;
        b_k[j] = idx >> 5;
        b_c[j] = idx & 31;
        b_d[j] = (uint32_t)(b_k[j] * 512 + ((b_c[j] ^ (b_k[j] & 7)) << 4));
    }

    const int nch = K >> 5;

#define LOAD_STAGE(stg, ch) do {                                              \
    uint32_t base = sb + (uint32_t)(stg) * 49152u;                            \
    const __half* ah = Ahi + (size_t)(bm * 128) * K + (ch) * 32;              \
    CPASYNC16(base + a_d0, ah + (size_t)ar0 * K + ac0 * 8);                   \
    CPASYNC16(base + a_d1, ah + (size_t)ar1 * K + ac1 * 8);                   \
    if (ALO) {                                                                \
        const __half* al = Alo + (size_t)(bm * 128) * K + (ch) * 32;          \
        CPASYNC16(base + 8192 + a_d0, al + (size_t)ar0 * K + ac0 * 8);        \
        CPASYNC16(base + 8192 + a_d1, al + (size_t)ar1 * K + ac1 * 8);        \
    }                                                                         \
    const __half* bh = Bhi + (size_t)((ch) * 32) * ldn + bcol;                \
    const __half* bl = Blo + (size_t)((ch) * 32) * ldn + bcol;                \
    _Pragma("unroll")                                                         \
    for (int j = 0; j < 4; j++) {                                             \
        CPASYNC16(base + 16384 + b_d[j], bh + (size_t)b_k[j] * ldn + b_c[j] * 8); \
        CPASYNC16(base + 32768 + b_d[j], bl + (size_t)b_k[j] * ldn + b_c[j] * 8); \
    }                                                                         \
} while (0)

    int mat = lane >> 3;
    int arb = wm * 64 + ((mat & 1) << 3) + (lane & 7);  // A row base
    int asw = (arb >> 1) & 3;
    int bkb = ((mat & 1) << 3) + (lane & 7);            // B k-row base
    int bcb = wn * 8 + (mat >> 1);                      // B chunk base (n)

    float acc[4][8][4];
#pragma unroll
    for (int i = 0; i < 4; i++)
#pragma unroll
        for (int j = 0; j < 8; j++)
#pragma unroll
            for (int q = 0; q < 4; q++) acc[i][j][q] = 0.f;

    LOAD_STAGE(0, 0);
    CP_COMMIT();
    if (nch > 1) {
        LOAD_STAGE(1, 1);
        CP_COMMIT();
    }

    int stg = 0;
    for (int ch = 0; ch < nch; ch++) {
        if (ch + 1 < nch) { CP_WAIT1(); } else { CP_WAIT0(); }
        __syncthreads();
        if (ch + 2 < nch) {
            int ns = stg + 2;
            if (ns >= 3) ns -= 3;
            LOAD_STAGE(ns, ch + 2);
            CP_COMMIT();
        }

        uint32_t Ab_hi = sb + (uint32_t)stg * 49152u;
        uint32_t Ab_lo = Ab_hi + 8192;
        uint32_t Bb_hi = Ab_hi + 16384;
        uint32_t Bb_lo = Ab_hi + 32768;

#pragma unroll
        for (int kh = 0; kh < 2; kh++) {
            uint32_t ac = (uint32_t)(((kh * 2 + (mat >> 1)) ^ asw) << 4);
            uint32_t a_hi[4][4], a_lo[4][4];
#pragma unroll
            for (int mt = 0; mt < 4; mt++) {
                uint32_t ro = (uint32_t)((arb + mt * 16) * 64);
                ldsm_x4(a_hi[mt], Ab_hi + ro + ac);
                if (ALO) ldsm_x4(a_lo[mt], Ab_lo + ro + ac);
            }
            int brow = kh * 16 + bkb;
            uint32_t bro = (uint32_t)(brow * 512);
            int bxor = brow & 7;
#pragma unroll
            for (int t = 0; t < 4; t++) {
                uint32_t b_hi[4], b_lo[4];
                uint32_t co = (uint32_t)(((bcb + t * 2) ^ bxor) << 4);
                ldsm_x4t(b_hi, Bb_hi + bro + co);
                ldsm_x4t(b_lo, Bb_lo + bro + co);
#pragma unroll
                for (int mt = 0; mt < 4; mt++)
#pragma unroll
                    for (int e = 0; e < 2; e++) {
                        float* d = acc[mt][t * 2 + e];
                        mma16816(d, a_hi[mt], b_hi[e * 2], b_hi[e * 2 + 1]);
                        mma16816(d, a_hi[mt], b_lo[e * 2], b_lo[e * 2 + 1]);
                        if (ALO)
                            mma16816(d, a_lo[mt], b_hi[e * 2], b_hi[e * 2 + 1]);
                    }
            }
        }
        if (++stg == 3) stg = 0;
    }
#undef LOAD_STAGE

#pragma unroll
    for (int mt = 0; mt < 4; mt++) {
        int row = bm * 128 + wm * 64 + mt * 16 + (lane >> 2);
#pragma unroll
        for (int nt = 0; nt < 8; nt++) {
            int col = bcol + wn * 64 + (nt >> 1) * 16 + (nt & 1) * 8 + (lane & 3) * 2;
            *(float2*)(C + (size_t)row * ldn + col) =
                make_float2(acc[mt][nt][0], acc[mt][nt][1]);
            *(float2*)(C + (size_t)(row + 8) * ldn + col) =
                make_float2(acc[mt][nt][2], acc[mt][nt][3]);
        }
    }
}

// ---------------- HMMA flash attention: 3-term QK and PV --------------------
__global__ __launch_bounds__(256, 1)
void flash_hmma_kernel(const __half* __restrict__ Qhi, const __half* __restrict__ Qlo,
                       const __half* __restrict__ KhiT, const __half* __restrict__ KloT,
                       const __half* __restrict__ Vhi, const __half* __restrict__ Vlo,
                       const int* __restrict__ amask,
                       __half* __restrict__ Ahi) {
    extern __shared__ char sm[];
    uint32_t sb = smem_u32(sm);
    float* sbias = (float*)(sm + 196608);

    int tid = threadIdx.x, wq = tid >> 5, lane = tid & 31;
    int mat = lane >> 3, l7 = lane & 7, qd = lane >> 2, l3 = lane & 3;
    int qb = (int)(gridDim.x - 1 - blockIdx.x);
    int h = blockIdx.y, kvh = h / REP;

    {
        const __half* qh = Qhi + ((size_t)(qb * 128) * NH + h) * HD;
        const __half* ql = Qlo + ((size_t)(qb * 128) * NH + h) * HD;
#pragma unroll
        for (int i = 0; i < 8; i++) {
            int idx = tid + i * 256;
            int row = idx >> 4, ch = idx & 15;
            uint32_t dst = sb + (uint32_t)(row * 256 + ((ch ^ (row & 7)) << 4));
            CPASYNC16(dst,         qh + (size_t)row * NHD + ch * 8);
            CPASYNC16(dst + 32768, ql + (size_t)row * NHD + ch * 8);
        }
    }

    auto load_kv = [&](int stage, int kb) {
        uint32_t base = sb + 65536u + (uint32_t)stage * 65536u;
        const __half* kh_ = KhiT + (size_t)kvh * HD * S_LEN + kb * 64;
        const __half* kl_ = KloT + (size_t)kvh * HD * S_LEN + kb * 64;
#pragma unroll
        for (int i = 0; i < 4; i++) {
            int idx = tid + i * 256;
            int row = idx >> 3, ch = idx & 7;
            uint32_t dst = base + (uint32_t)(row * 128 + ((ch ^ (row & 7)) << 4));
            CPASYNC16(dst,         kh_ + (size_t)row * S_LEN + ch * 8);
            CPASYNC16(dst + 16384, kl_ + (size_t)row * S_LEN + ch * 8);
        }
        const __half* vh_ = Vhi + ((size_t)(kb * 64) * NKV + kvh) * HD;
        const __half* vl_ = Vlo + ((size_t)(kb * 64) * NKV + kvh) * HD;
#pragma unroll
        for (int i = 0; i < 4; i++) {
            int idx = tid + i * 256;
            int row = idx >> 4, ch = idx & 15;
            uint32_t dst = base + 32768u + (uint32_t)(row * 256 + ((ch ^ (row & 7)) << 4));
            CPASYNC16(dst,         vh_ + (size_t)row * NKV * HD + ch * 8);
            CPASYNC16(dst + 16384, vl_ + (size_t)row * NKV * HD + ch * 8);
        }
    };

    load_kv(0, 0);
    CP_COMMIT();

    float o[16][4];
#pragma unroll
    for (int i = 0; i < 16; i++)
#pragma unroll
        for (int j = 0; j < 4; j++) o[i][j] = 0.f;
    float m0 = -1e30f, m1 = -1e30f, l0 = 0.f, l1 = 0.f;

    int kbmax = 2 * qb + 1;
    int r0g = qb * 128 + wq * 16 + qd, r1g = r0g + 8;
    int arow = wq * 16 + ((mat & 1) << 3) + l7;
    int brow0 = ((mat & 1) << 3) + l7;

    for (int kb = 0; kb <= kbmax; kb++) {
        if (kb < kbmax) {
            load_kv((kb + 1) & 1, kb + 1);
            CP_COMMIT();
            CP_WAIT1();
        } else {
            CP_WAIT0();
        }
        if (tid < 64) sbias[tid] = amask[kb * 64 + tid] ? 0.f : -1e30f;
        __syncthreads();

        uint32_t Kb = sb + 65536u + (uint32_t)(kb & 1) * 65536u;
        uint32_t Vb = Kb + 32768u;

        float s[8][4];
#pragma unroll
        for (int i = 0; i < 8; i++)
#pragma unroll
            for (int j = 0; j < 4; j++) s[i][j] = 0.f;

#pragma unroll
        for (int kh2 = 0; kh2 < 8; kh2++) {
            uint32_t a_hi[4], a_lo[4];
            int ach = kh2 * 2 + (mat >> 1);
            uint32_t aaddr = sb + (uint32_t)(arow * 256 + ((ach ^ (arow & 7)) << 4));
            ldsm_x4(a_hi, aaddr);
            ldsm_x4(a_lo, aaddr + 32768);
            int brow = kh2 * 16 + brow0;
#pragma unroll
            for (int hf = 0; hf < 2; hf++) {
                uint32_t b_hi[2][4], b_lo[2][4];
#pragma unroll
                for (int p = 0; p < 2; p++) {
                    int bch = (hf * 2 + p) * 2 + (mat >> 1);
                    uint32_t baddr = Kb + (uint32_t)(brow * 128 + ((bch ^ (brow & 7)) << 4));
                    ldsm_x4t(b_hi[p], baddr);
                    ldsm_x4t(b_lo[p], baddr + 16384);
                }
#pragma unroll
                for (int p = 0; p < 2; p++)
#pragma unroll
                    for (int e = 0; e < 2; e++) {
                        int nt = hf * 4 + p * 2 + e;
                        mma16816(s[nt], a_hi, b_hi[p][e * 2], b_hi[p][e * 2 + 1]);
                        mma16816(s[nt], a_hi, b_lo[p][e * 2], b_lo[p][e * 2 + 1]);
                        mma16816(s[nt], a_lo, b_hi[p][e * 2], b_hi[p][e * 2 + 1]);
                    }
            }
        }

#pragma unroll
        for (int nt = 0; nt < 8; nt++) {
            int c = nt * 8 + 2 * l3;
            float b0 = sbias[c], b1 = sbias[c + 1];
            s[nt][0] += b0; s[nt][1] += b1; s[nt][2] += b0; s[nt][3] += b1;
        }
        if (kb >= 2 * qb) {
            int cbase = kb * 64 + 2 * l3;
#pragma unroll
            for (int nt = 0; nt < 8; nt++) {
                int c0 = cbase + nt * 8, c1 = c0 + 1;
                if (c0 > r0g) s[nt][0] = -1e30f;
                if (c1 > r0g) s[nt][1] = -1e30f;
                if (c0 > r1g) s[nt][2] = -1e30f;
                if (c1 > r1g) s[nt][3] = -1e30f;
            }
        }

        float mx0 = -1e30f, mx1 = -1e30f;
#pragma unroll
        for (int nt = 0; nt < 8; nt++) {
            mx0 = fmaxf(mx0, fmaxf(s[nt][0], s[nt][1]));
            mx1 = fmaxf(mx1, fmaxf(s[nt][2], s[nt][3]));
        }
        mx0 = fmaxf(mx0, __shfl_xor_sync(0xffffffffu, mx0, 1));
        mx0 = fmaxf(mx0, __shfl_xor_sync(0xffffffffu, mx0, 2));
        mx1 = fmaxf(mx1, __shfl_xor_sync(0xffffffffu, mx1, 1));
        mx1 = fmaxf(mx1, __shfl_xor_sync(0xffffffffu, mx1, 2));
        float mn0 = fmaxf(m0, mx0), mn1 = fmaxf(m1, mx1);
        float al0 = __expf(m0 - mn0), al1 = __expf(m1 - mn1);
        m0 = mn0; m1 = mn1;
        float rs0 = 0.f, rs1 = 0.f;
#pragma unroll
        for (int nt = 0; nt < 8; nt++) {
            s[nt][0] = __expf(s[nt][0] - mn0); rs0 += s[nt][0];
            s[nt][1] = __expf(s[nt][1] - mn0); rs0 += s[nt][1];
            s[nt][2] = __expf(s[nt][2] - mn1); rs1 += s[nt][2];
            s[nt][3] = __expf(s[nt][3] - mn1); rs1 += s[nt][3];
        }
        rs0 += __shfl_xor_sync(0xffffffffu, rs0, 1);
        rs0 += __shfl_xor_sync(0xffffffffu, rs0, 2);
        rs1 += __shfl_xor_sync(0xffffffffu, rs1, 1);
        rs1 += __shfl_xor_sync(0xffffffffu, rs1, 2);
        l0 = l0 * al0 + rs0;
        l1 = l1 * al1 + rs1;
#pragma unroll
        for (int nt = 0; nt < 16; nt++) {
            o[nt][0] *= al0; o[nt][1] *= al0;
            o[nt][2] *= al1; o[nt][3] *= al1;
        }

#pragma unroll
        for (int j = 0; j < 4; j++) {
            uint32_t phi[4], plo[4];
            split2(s[2 * j][0],     s[2 * j][1],     phi[0], plo[0]);
            split2(s[2 * j][2],     s[2 * j][3],     phi[1], plo[1]);
            split2(s[2 * j + 1][0], s[2 * j + 1][1], phi[2], plo[2]);
            split2(s[2 * j + 1][2], s[2 * j + 1][3], phi[3], plo[3]);
            int vrow = j * 16 + ((mat & 1) << 3) + l7;
#pragma unroll
            for (int nb = 0; nb < 8; nb++) {
                uint32_t v_hi[4], v_lo[4];
                int vch = nb * 2 + (mat >> 1);
                uint32_t vaddr = Vb + (uint32_t)(vrow * 256 + ((vch ^ (vrow & 7)) << 4));
                ldsm_x4t(v_hi, vaddr);
                ldsm_x4t(v_lo, vaddr + 16384);
#pragma unroll
                for (int e = 0; e < 2; e++) {
                    int nt = nb * 2 + e;
                    mma16816(o[nt], phi, v_hi[e * 2], v_hi[e * 2 + 1]);
                    mma16816(o[nt], phi, v_lo[e * 2], v_lo[e * 2 + 1]);
                    mma16816(o[nt], plo, v_hi[e * 2], v_hi[e * 2 + 1]);
                }
            }
        }
        __syncthreads();
    }

    float inv0 = 1.f / l0, inv1 = 1.f / l1;
    size_t ro0 = (size_t)r0g * NHD + h * HD + 2 * l3;
    size_t ro1 = (size_t)r1g * NHD + h * HD + 2 * l3;
#pragma unroll
    for (int nt = 0; nt < 16; nt++) {
        *(__half2*)(Ahi + ro0 + nt * 8) =
            __floats2half2_rn(o[nt][0] * inv0, o[nt][1] * inv0);
        *(__half2*)(Ahi + ro1 + nt * 8) =
            __floats2half2_rn(o[nt][2] * inv1, o[nt][3] * inv1);
    }
}

// ---------------- launcher ---------------------------------------------------
extern "C" void kernel_launch(void* const* d_in, const int* in_sizes, int n_in,
                              void* d_out, int out_size) {
    const float* x     = (const float*)d_in[0];
    const int*   amask = (const int*)  d_in[1];
    const int*   pos   = (const int*)  d_in[2];
    const float* Wq    = (const float*)d_in[3];
    const float* Wk    = (const float*)d_in[4];
    const float* Wv    = (const float*)d_in[5];
    const float* Wo    = (const float*)d_in[6];
    float* out = (float*)d_out;

    float *qp, *kp, *vp;
    cudaGetSymbolAddress((void**)&qp, g_q);
    cudaGetSymbolAddress((void**)&kp, g_k);
    cudaGetSymbolAddress((void**)&vp, g_v);
    __half *xh, *xl, *wqh, *wql, *wkh, *wkl, *wvh, *wvl, *woh, *wol, *ah;
    __half *qhi, *qlo, *khiT, *kloT, *vhi, *vlo;
    cudaGetSymbolAddress((void**)&xh,  g_x_hi);  cudaGetSymbolAddress((void**)&xl,  g_x_lo);
    cudaGetSymbolAddress((void**)&wqh, g_wq_hi); cudaGetSymbolAddress((void**)&wql, g_wq_lo);
    cudaGetSymbolAddress((void**)&wkh, g_wk_hi); cudaGetSymbolAddress((void**)&wkl, g_wk_lo);
    cudaGetSymbolAddress((void**)&wvh, g_wv_hi); cudaGetSymbolAddress((void**)&wvl, g_wv_lo);
    cudaGetSymbolAddress((void**)&woh, g_wo_hi); cudaGetSymbolAddress((void**)&wol, g_wo_lo);
    cudaGetSymbolAddress((void**)&ah,  g_a_hi);
    cudaGetSymbolAddress((void**)&qhi, g_qhi);   cudaGetSymbolAddress((void**)&qlo, g_qlo);
    cudaGetSymbolAddress((void**)&khiT, g_khiT); cudaGetSymbolAddress((void**)&kloT, g_kloT);
    cudaGetSymbolAddress((void**)&vhi, g_vhi);   cudaGetSymbolAddress((void**)&vlo, g_vlo);

    // 0) fused split of x + all weights
    const int SPLIT_TOT = (S_LEN * HID + HID * NH * HD + 2 * HID * NKV * HD
                           + NH * HD * HID) / 4;
    split_all_kernel<<<(SPLIT_TOT + 255) / 256, 256>>>(
        x, Wq, Wk, Wv, Wo, xh, xl, wqh, wql, wkh, wkl, wvh, wvl, woh, wol);

    // 1) RoPE table
    build_rope_kernel<<<(S_LEN * 64 + 255) / 256, 256>>>(pos);

    // 2) fused QKV projection (HMMA, 3-term, 128x256 tiles)
    const int gemm_smem = 147456;
    cudaFuncSetAttribute(gemm_hmma_kernel<1, 1>,
                         cudaFuncAttributeMaxDynamicSharedMemorySize, gemm_smem);
    cudaFuncSetAttribute(gemm_hmma_kernel<0, 0>,
                         cudaFuncAttributeMaxDynamicSharedMemorySize, gemm_smem);
    gemm_hmma_kernel<1, 1><<<dim3(18, 16), 256, gemm_smem>>>(
        xh, xl, wqh, wql, wkh, wkl, wvh, wvl, qp, kp, vp, HID, NH * HD);

    // 3) fused RoPE+split (Q, K^T) + V split
    const int PREP_TOT = S_LEN * NH * 64 + S_LEN * NKV * 64 + S_LEN * NKV * HD / 4;
    prep_attention_kernel<<<(PREP_TOT + 255) / 256, 256>>>(
        qp, kp, vp, qhi, qlo, khiT, kloT, vhi, vlo);

    // 4) HMMA flash attention -> fp16 hi output
    const int flash_smem = 196864;
    cudaFuncSetAttribute(flash_hmma_kernel,
                         cudaFuncAttributeMaxDynamicSharedMemorySize, flash_smem);
    flash_hmma_kernel<<<dim3(S_LEN / 128, NH), 256, flash_smem>>>(
        qhi, qlo, khiT, kloT, vhi, vlo, amask, ah);

    // 5) O projection (HMMA, 2-term, 128x256 tiles) -> final output
    gemm_hmma_kernel<0, 0><<<dim3(14, 16), 256, gemm_smem>>>(
        ah, nullptr, woh, wol, nullptr, nullptr, nullptr, nullptr,
        out, nullptr, nullptr, HID, HID);
}

// round 10
// speedup vs baseline: 1.1888x; 1.1888x over previous
#include <cuda_runtime.h>
#include <cuda_fp16.h>
#include <math.h>
#include <cstdint>

#define S_LEN 2048
#define HID   3584
#define NH    28
#define NKV   4
#define HD    128
#define REP   7
#define NHD   (NH * HD)
#define QK_SCALE 0.0883883476483184406f

// ---------------- scratch (device globals; no allocations allowed) ----------
__device__ float g_q[S_LEN * NH * HD];
__device__ float g_k[S_LEN * NKV * HD];
__device__ float g_v[S_LEN * NKV * HD];
__device__ float g_sin[S_LEN * 64];
__device__ float g_cos[S_LEN * 64];

__device__ __align__(16) __half g_x_hi[S_LEN * HID];
__device__ __align__(16) __half g_x_lo[S_LEN * HID];
__device__ __align__(16) __half g_wq_hi[HID * NH * HD];
__device__ __align__(16) __half g_wq_lo[HID * NH * HD];
__device__ __align__(16) __half g_wk_hi[HID * NKV * HD];
__device__ __align__(16) __half g_wk_lo[HID * NKV * HD];
__device__ __align__(16) __half g_wv_hi[HID * NKV * HD];
__device__ __align__(16) __half g_wv_lo[HID * NKV * HD];
__device__ __align__(16) __half g_wo_hi[NH * HD * HID];
__device__ __align__(16) __half g_a_hi[S_LEN * NH * HD];
// flash operands
__device__ __align__(16) __half g_qhi[S_LEN * NH * HD];
__device__ __align__(16) __half g_qlo[S_LEN * NH * HD];
__device__ __align__(16) __half g_khiT[NKV * HD * S_LEN];   // [NKV][HD][S]
__device__ __align__(16) __half g_kloT[NKV * HD * S_LEN];
__device__ __align__(16) __half g_vhi[S_LEN * NKV * HD];
__device__ __align__(16) __half g_vlo[S_LEN * NKV * HD];

// ---------------- HMMA helpers (base-target instructions only) --------------
__device__ __forceinline__ uint32_t smem_u32(const void* p) {
    uint32_t a;
    asm("{ .reg .u64 t; cvta.to.shared.u64 t, %1; cvt.u32.u64 %0, t; }"
        : "=r"(a) : "l"(p));
    return a;
}
__device__ __forceinline__ void ldsm_x4(uint32_t* r, uint32_t addr) {
    asm volatile("ldmatrix.sync.aligned.m8n8.x4.shared.b16 {%0,%1,%2,%3}, [%4];"
        : "=r"(r[0]), "=r"(r[1]), "=r"(r[2]), "=r"(r[3]) : "r"(addr));
}
__device__ __forceinline__ void ldsm_x4t(uint32_t* r, uint32_t addr) {
    asm volatile("ldmatrix.sync.aligned.m8n8.x4.trans.shared.b16 {%0,%1,%2,%3}, [%4];"
        : "=r"(r[0]), "=r"(r[1]), "=r"(r[2]), "=r"(r[3]) : "r"(addr));
}
__device__ __forceinline__ void mma16816(float* d, const uint32_t* a,
                                         uint32_t b0, uint32_t b1) {
    asm volatile(
        "mma.sync.aligned.m16n8k16.row.col.f32.f16.f16.f32 "
        "{%0,%1,%2,%3}, {%4,%5,%6,%7}, {%8,%9}, {%0,%1,%2,%3};"
        : "+f"(d[0]), "+f"(d[1]), "+f"(d[2]), "+f"(d[3])
        : "r"(a[0]), "r"(a[1]), "r"(a[2]), "r"(a[3]), "r"(b0), "r"(b1));
}
#define CPASYNC16(dst, src) \
    asm volatile("cp.async.cg.shared.global [%0], [%1], 16;" \
                 :: "r"(dst), "l"(src) : "memory")
#define CP_COMMIT() asm volatile("cp.async.commit_group;" ::: "memory")
#define CP_WAIT1()  asm volatile("cp.async.wait_group 1;" ::: "memory")
#define CP_WAIT0()  asm volatile("cp.async.wait_group 0;" ::: "memory")

// pack two floats -> fp16x2 in a u32 (replaces nonexistent __half2_as_uint)
__device__ __forceinline__ uint32_t pack_h2(float x, float y) {
    __half hx = __float2half_rn(x), hy = __float2half_rn(y);
    return (uint32_t)__half_as_ushort(hx) | ((uint32_t)__half_as_ushort(hy) << 16);
}

__device__ __forceinline__ void split4_at(const float* __restrict__ src,
                                          __half* __restrict__ hi,
                                          __half* __restrict__ lo, int i) {
    float4 v = ((const float4*)src)[i];
    __half h0 = __float2half_rn(v.x), h1 = __float2half_rn(v.y);
    __half h2 = __float2half_rn(v.z), h3 = __float2half_rn(v.w);
    __half l0 = __float2half_rn(v.x - __half2float(h0));
    __half l1 = __float2half_rn(v.y - __half2float(h1));
    __half l2 = __float2half_rn(v.z - __half2float(h2));
    __half l3 = __float2half_rn(v.w - __half2float(h3));
    ((uint2*)hi)[i] = make_uint2(
        (uint32_t)__half_as_ushort(h0) | ((uint32_t)__half_as_ushort(h1) << 16),
        (uint32_t)__half_as_ushort(h2) | ((uint32_t)__half_as_ushort(h3) << 16));
    ((uint2*)lo)[i] = make_uint2(
        (uint32_t)__half_as_ushort(l0) | ((uint32_t)__half_as_ushort(l1) << 16),
        (uint32_t)__half_as_ushort(l2) | ((uint32_t)__half_as_ushort(l3) << 16));
}
__device__ __forceinline__ void trunc4_at(const float* __restrict__ src,
                                          __half* __restrict__ hi, int i) {
    float4 v = ((const float4*)src)[i];
    ((uint2*)hi)[i] = make_uint2(pack_h2(v.x, v.y), pack_h2(v.z, v.w));
}

// ---------------- fused split of x + weights (Wo: hi only) -------------------
__global__ void split_all_kernel(const float* __restrict__ x,
                                 const float* __restrict__ wq,
                                 const float* __restrict__ wk,
                                 const float* __restrict__ wv,
                                 const float* __restrict__ wo,
                                 __half* xh, __half* xl, __half* qh, __half* ql,
                                 __half* kh, __half* kl, __half* vh, __half* vl,
                                 __half* oh) {
    const int C0 = S_LEN * HID / 4;
    const int C1 = C0 + HID * NH * HD / 4;
    const int C2 = C1 + HID * NKV * HD / 4;
    const int C3 = C2 + HID * NKV * HD / 4;
    const int C4 = C3 + NH * HD * HID / 4;
    int i = blockIdx.x * blockDim.x + threadIdx.x;
    if (i >= C4) return;
    if (i < C0)      split4_at(x,  xh, xl, i);
    else if (i < C1) split4_at(wq, qh, ql, i - C0);
    else if (i < C2) split4_at(wk, kh, kl, i - C1);
    else if (i < C3) split4_at(wv, vh, vl, i - C2);
    else             trunc4_at(wo, oh, i - C3);
}

// ---------------- RoPE sin/cos table -----------------------------------------
__global__ void build_rope_kernel(const int* __restrict__ pos) {
    int idx = blockIdx.x * blockDim.x + threadIdx.x;
    if (idx >= S_LEN * 64) return;
    int i = idx & 63;
    int s = idx >> 6;
    double inv = exp(-((double)i / 64.0) * log(1.0e6));
    double ang = (double)pos[s] * inv;
    g_sin[idx] = (float)sin(ang);
    g_cos[idx] = (float)cos(ang);
}

// ---------------- fused: RoPE+split Q | RoPE+split K^T | split V -------------
__global__ void prep_attention_kernel(const float* __restrict__ Q,
                                      const float* __restrict__ Kc,
                                      const float* __restrict__ V,
                                      __half* __restrict__ qhi, __half* __restrict__ qlo,
                                      __half* __restrict__ khiT, __half* __restrict__ kloT,
                                      __half* __restrict__ vhi, __half* __restrict__ vlo) {
    const int R0 = S_LEN * NH * 64;
    const int R1 = R0 + S_LEN * NKV * 64;
    const int R2 = R1 + S_LEN * NKV * HD / 4;
    int idx = blockIdx.x * blockDim.x + threadIdx.x;
    if (idx >= R2) return;

    if (idx < R0) {
        int i = idx & 63;
        int t = idx >> 6;
        int h = t % NH;
        int s = t / NH;
        float sn = g_sin[s * 64 + i], cs = g_cos[s * 64 + i];
        const float* p = Q + ((size_t)s * NH + h) * HD;
        float x0 = p[i], x1 = p[i + 64];
        float y0 = (x0 * cs - x1 * sn) * QK_SCALE;
        float y1 = (x1 * cs + x0 * sn) * QK_SCALE;
        size_t o = ((size_t)s * NH + h) * HD;
        __half h0 = __float2half_rn(y0);
        qhi[o + i] = h0;
        qlo[o + i] = __float2half_rn(y0 - __half2float(h0));
        __half h1 = __float2half_rn(y1);
        qhi[o + i + 64] = h1;
        qlo[o + i + 64] = __float2half_rn(y1 - __half2float(h1));
    } else if (idx < R1) {
        int j = idx - R0;
        int s = j & (S_LEN - 1);
        int t = j >> 11;
        int i = t & 63;
        int kvh = t >> 6;
        float sn = g_sin[s * 64 + i], cs = g_cos[s * 64 + i];
        const float* p = Kc + ((size_t)s * NKV + kvh) * HD;
        float x0 = p[i], x1 = p[i + 64];
        float y0 = x0 * cs - x1 * sn;
        float y1 = x1 * cs + x0 * sn;
        size_t o0 = ((size_t)kvh * HD + i) * S_LEN + s;
        size_t o1 = ((size_t)kvh * HD + i + 64) * S_LEN + s;
        __half h0 = __float2half_rn(y0);
        khiT[o0] = h0;
        kloT[o0] = __float2half_rn(y0 - __half2float(h0));
        __half h1 = __float2half_rn(y1);
        khiT[o1] = h1;
        kloT[o1] = __float2half_rn(y1 - __half2float(h1));
    } else {
        split4_at(V, vhi, vlo, idx - R1);
    }
}

// ---------------- HMMA GEMM (R7 config): 128x128 tile, 3-stage pipeline ------
// BK=32, 8 warps (2M x 4N), warp tile 64x32. Stage 32KB.
// Term control: ALO adds a_lo*b_hi; BLO adds a_hi*b_lo. QKV: <1,1,1> (3-term).
// O-proj: <0,0,0> (pure fp16, 1-term; Alo/Blo never loaded).
template <int FUSED, int ALO, int BLO>
__global__ __launch_bounds__(256)
void gemm_hmma_kernel(const __half* __restrict__ Ahi, const __half* __restrict__ Alo,
                      const __half* __restrict__ Bhi0, const __half* __restrict__ Blo0,
                      const __half* __restrict__ Bhi1, const __half* __restrict__ Blo1,
                      const __half* __restrict__ Bhi2, const __half* __restrict__ Blo2,
                      float* __restrict__ C0, float* __restrict__ C1,
                      float* __restrict__ C2, int K, int N0) {
    extern __shared__ char smem[];
    uint32_t sb = smem_u32(smem);
    // stage = 32KB: A_hi[0,8K) A_lo[8K,16K) B_hi[16K,24K) B_lo[24K,32K); 3 stages

    int tid = threadIdx.x, wid = tid >> 5, lane = tid & 31;
    int bn = blockIdx.x, bm = blockIdx.y;
    int wm = wid & 1, wn = wid >> 1;

    const __half* Bhi = Bhi0;
    const __half* Blo = Blo0;
    float* C = C0;
    int ldn = N0, bcol = bn * 128;
    if (FUSED) {
        if (bn >= 28 && bn < 32) {
            Bhi = Bhi1; Blo = Blo1; C = C1; ldn = NKV * HD; bcol = (bn - 28) * 128;
        } else if (bn >= 32) {
            Bhi = Bhi2; Blo = Blo2; C = C2; ldn = NKV * HD; bcol = (bn - 32) * 128;
        }
    }

    int ar0 = tid >> 2, ac0 = tid & 3;
    int ar1 = (tid + 256) >> 2, ac1 = tid & 3;
    int br0 = tid >> 4, bc0 = tid & 15;
    int br1 = (tid + 256) >> 4, bc1 = tid & 15;
    uint32_t a_d0 = (uint32_t)(ar0 * 64 + ((ac0 ^ ((ar0 >> 1) & 3)) << 4));
    uint32_t a_d1 = (uint32_t)(ar1 * 64 + ((ac1 ^ ((ar1 >> 1) & 3)) << 4));
    uint32_t b_d0 = (uint32_t)(br0 * 256 + ((bc0 ^ (br0 & 7)) << 4));
    uint32_t b_d1 = (uint32_t)(br1 * 256 + ((bc1 ^ (br1 & 7)) << 4));

    const int nch = K >> 5;

#define LOAD_STAGE(stg, ch) do {                                              \
    uint32_t base = sb + (uint32_t)(stg) * 32768u;                            \
    const __half* ah = Ahi + (size_t)(bm * 128) * K + (ch) * 32;              \
    CPASYNC16(base + a_d0, ah + (size_t)ar0 * K + ac0 * 8);                   \
    CPASYNC16(base + a_d1, ah + (size_t)ar1 * K + ac1 * 8);                   \
    if (ALO) {                                                                \
        const __half* al = Alo + (size_t)(bm * 128) * K + (ch) * 32;          \
        CPASYNC16(base + 8192 + a_d0, al + (size_t)ar0 * K + ac0 * 8);        \
        CPASYNC16(base + 8192 + a_d1, al + (size_t)ar1 * K + ac1 * 8);        \
    }                                                                         \
    const __half* bh = Bhi + (size_t)((ch) * 32) * ldn + bcol;                \
    CPASYNC16(base + 16384 + b_d0, bh + (size_t)br0 * ldn + bc0 * 8);         \
    CPASYNC16(base + 16384 + b_d1, bh + (size_t)br1 * ldn + bc1 * 8);         \
    if (BLO) {                                                                \
        const __half* bl = Blo + (size_t)((ch) * 32) * ldn + bcol;            \
        CPASYNC16(base + 24576 + b_d0, bl + (size_t)br0 * ldn + bc0 * 8);     \
        CPASYNC16(base + 24576 + b_d1, bl + (size_t)br1 * ldn + bc1 * 8);     \
    }                                                                         \
} while (0)

    int mat = lane >> 3;
    int arb = wm * 64 + ((mat & 1) << 3) + (lane & 7);
    int asw = (arb >> 1) & 3;
    int bkb = ((mat & 1) << 3) + (lane & 7);
    int bsw = lane & 7;
    int bnc = wn * 4 + (mat >> 1);

    float acc[4][4][4];
#pragma unroll
    for (int i = 0; i < 4; i++)
#pragma unroll
        for (int j = 0; j < 4; j++)
#pragma unroll
            for (int q = 0; q < 4; q++) acc[i][j][q] = 0.f;

    LOAD_STAGE(0, 0);
    CP_COMMIT();
    if (nch > 1) {
        LOAD_STAGE(1, 1);
        CP_COMMIT();
    }

    int stg = 0;
    for (int ch = 0; ch < nch; ch++) {
        if (ch + 1 < nch) { CP_WAIT1(); } else { CP_WAIT0(); }
        __syncthreads();
        if (ch + 2 < nch) {
            int ns = stg + 2;
            if (ns >= 3) ns -= 3;
            LOAD_STAGE(ns, ch + 2);
            CP_COMMIT();
        }

        uint32_t Ab_hi = sb + (uint32_t)stg * 32768u;
        uint32_t Ab_lo = Ab_hi + 8192;
        uint32_t Bb_hi = Ab_hi + 16384;
        uint32_t Bb_lo = Ab_hi + 24576;

#pragma unroll
        for (int kh = 0; kh < 2; kh++) {
            uint32_t ac = (uint32_t)(((kh * 2 + (mat >> 1)) ^ asw) << 4);
            uint32_t a_hi[4][4], a_lo[4][4];
#pragma unroll
            for (int mt = 0; mt < 4; mt++) {
                uint32_t ro = (uint32_t)((arb + mt * 16) * 64);
                ldsm_x4(a_hi[mt], Ab_hi + ro + ac);
                if (ALO) ldsm_x4(a_lo[mt], Ab_lo + ro + ac);
            }
            uint32_t bro = (uint32_t)((kh * 16 + bkb) * 256);
            uint32_t b_hi[2][4], b_lo[2][4];
#pragma unroll
            for (int p = 0; p < 2; p++) {
                uint32_t co = (uint32_t)((((bnc + p * 2)) ^ bsw) << 4);
                ldsm_x4t(b_hi[p], Bb_hi + bro + co);
                if (BLO) ldsm_x4t(b_lo[p], Bb_lo + bro + co);
            }
#pragma unroll
            for (int mt = 0; mt < 4; mt++)
#pragma unroll
                for (int p = 0; p < 2; p++) {
                    mma16816(acc[mt][p * 2],     a_hi[mt], b_hi[p][0], b_hi[p][1]);
                    mma16816(acc[mt][p * 2 + 1], a_hi[mt], b_hi[p][2], b_hi[p][3]);
                    if (BLO) {
                        mma16816(acc[mt][p * 2],     a_hi[mt], b_lo[p][0], b_lo[p][1]);
                        mma16816(acc[mt][p * 2 + 1], a_hi[mt], b_lo[p][2], b_lo[p][3]);
                    }
                    if (ALO) {
                        mma16816(acc[mt][p * 2],     a_lo[mt], b_hi[p][0], b_hi[p][1]);
                        mma16816(acc[mt][p * 2 + 1], a_lo[mt], b_hi[p][2], b_hi[p][3]);
                    }
                }
        }
        if (++stg == 3) stg = 0;
    }
#undef LOAD_STAGE

#pragma unroll
    for (int mt = 0; mt < 4; mt++) {
        int row = bm * 128 + wm * 64 + mt * 16 + (lane >> 2);
#pragma unroll
        for (int nt = 0; nt < 4; nt++) {
            int col = bcol + wn * 32 + (nt >> 1) * 16 + (nt & 1) * 8 + (lane & 3) * 2;
            *(float2*)(C + (size_t)row * ldn + col) =
                make_float2(acc[mt][nt][0], acc[mt][nt][1]);
            *(float2*)(C + (size_t)(row + 8) * ldn + col) =
                make_float2(acc[mt][nt][2], acc[mt][nt][3]);
        }
    }
}

// ---------------- HMMA flash attention: 3-term QK, 2-term PV ----------------
__global__ __launch_bounds__(256, 1)
void flash_hmma_kernel(const __half* __restrict__ Qhi, const __half* __restrict__ Qlo,
                       const __half* __restrict__ KhiT, const __half* __restrict__ KloT,
                       const __half* __restrict__ Vhi, const __half* __restrict__ Vlo,
                       const int* __restrict__ amask,
                       __half* __restrict__ Ahi) {
    extern __shared__ char sm[];
    uint32_t sb = smem_u32(sm);
    float* sbias = (float*)(sm + 196608);

    int tid = threadIdx.x, wq = tid >> 5, lane = tid & 31;
    int mat = lane >> 3, l7 = lane & 7, qd = lane >> 2, l3 = lane & 3;
    int qb = (int)(gridDim.x - 1 - blockIdx.x);
    int h = blockIdx.y, kvh = h / REP;

    {
        const __half* qh = Qhi + ((size_t)(qb * 128) * NH + h) * HD;
        const __half* ql = Qlo + ((size_t)(qb * 128) * NH + h) * HD;
#pragma unroll
        for (int i = 0; i < 8; i++) {
            int idx = tid + i * 256;
            int row = idx >> 4, ch = idx & 15;
            uint32_t dst = sb + (uint32_t)(row * 256 + ((ch ^ (row & 7)) << 4));
            CPASYNC16(dst,         qh + (size_t)row * NHD + ch * 8);
            CPASYNC16(dst + 32768, ql + (size_t)row * NHD + ch * 8);
        }
    }

    auto load_kv = [&](int stage, int kb) {
        uint32_t base = sb + 65536u + (uint32_t)stage * 65536u;
        const __half* kh_ = KhiT + (size_t)kvh * HD * S_LEN + kb * 64;
        const __half* kl_ = KloT + (size_t)kvh * HD * S_LEN + kb * 64;
#pragma unroll
        for (int i = 0; i < 4; i++) {
            int idx = tid + i * 256;
            int row = idx >> 3, ch = idx & 7;
            uint32_t dst = base + (uint32_t)(row * 128 + ((ch ^ (row & 7)) << 4));
            CPASYNC16(dst,         kh_ + (size_t)row * S_LEN + ch * 8);
            CPASYNC16(dst + 16384, kl_ + (size_t)row * S_LEN + ch * 8);
        }
        const __half* vh_ = Vhi + ((size_t)(kb * 64) * NKV + kvh) * HD;
        const __half* vl_ = Vlo + ((size_t)(kb * 64) * NKV + kvh) * HD;
#pragma unroll
        for (int i = 0; i < 4; i++) {
            int idx = tid + i * 256;
            int row = idx >> 4, ch = idx & 15;
            uint32_t dst = base + 32768u + (uint32_t)(row * 256 + ((ch ^ (row & 7)) << 4));
            CPASYNC16(dst,         vh_ + (size_t)row * NKV * HD + ch * 8);
            CPASYNC16(dst + 16384, vl_ + (size_t)row * NKV * HD + ch * 8);
        }
    };

    load_kv(0, 0);
    CP_COMMIT();

    float o[16][4];
#pragma unroll
    for (int i = 0; i < 16; i++)
#pragma unroll
        for (int j = 0; j < 4; j++) o[i][j] = 0.f;
    float m0 = -1e30f, m1 = -1e30f, l0 = 0.f, l1 = 0.f;

    int kbmax = 2 * qb + 1;
    int r0g = qb * 128 + wq * 16 + qd, r1g = r0g + 8;
    int arow = wq * 16 + ((mat & 1) << 3) + l7;
    int brow0 = ((mat & 1) << 3) + l7;

    for (int kb = 0; kb <= kbmax; kb++) {
        if (kb < kbmax) {
            load_kv((kb + 1) & 1, kb + 1);
            CP_COMMIT();
            CP_WAIT1();
        } else {
            CP_WAIT0();
        }
        if (tid < 64) sbias[tid] = amask[kb * 64 + tid] ? 0.f : -1e30f;
        __syncthreads();

        uint32_t Kb = sb + 65536u + (uint32_t)(kb & 1) * 65536u;
        uint32_t Vb = Kb + 32768u;

        float s[8][4];
#pragma unroll
        for (int i = 0; i < 8; i++)
#pragma unroll
            for (int j = 0; j < 4; j++) s[i][j] = 0.f;

#pragma unroll
        for (int kh2 = 0; kh2 < 8; kh2++) {
            uint32_t a_hi[4], a_lo[4];
            int ach = kh2 * 2 + (mat >> 1);
            uint32_t aaddr = sb + (uint32_t)(arow * 256 + ((ach ^ (arow & 7)) << 4));
            ldsm_x4(a_hi, aaddr);
            ldsm_x4(a_lo, aaddr + 32768);
            int brow = kh2 * 16 + brow0;
#pragma unroll
            for (int hf = 0; hf < 2; hf++) {
                uint32_t b_hi[2][4], b_lo[2][4];
#pragma unroll
                for (int p = 0; p < 2; p++) {
                    int bch = (hf * 2 + p) * 2 + (mat >> 1);
                    uint32_t baddr = Kb + (uint32_t)(brow * 128 + ((bch ^ (brow & 7)) << 4));
                    ldsm_x4t(b_hi[p], baddr);
                    ldsm_x4t(b_lo[p], baddr + 16384);
                }
#pragma unroll
                for (int p = 0; p < 2; p++)
#pragma unroll
                    for (int e = 0; e < 2; e++) {
                        int nt = hf * 4 + p * 2 + e;
                        mma16816(s[nt], a_hi, b_hi[p][e * 2], b_hi[p][e * 2 + 1]);
                        mma16816(s[nt], a_hi, b_lo[p][e * 2], b_lo[p][e * 2 + 1]);
                        mma16816(s[nt], a_lo, b_hi[p][e * 2], b_hi[p][e * 2 + 1]);
                    }
            }
        }

#pragma unroll
        for (int nt = 0; nt < 8; nt++) {
            int c = nt * 8 + 2 * l3;
            float b0 = sbias[c], b1 = sbias[c + 1];
            s[nt][0] += b0; s[nt][1] += b1; s[nt][2] += b0; s[nt][3] += b1;
        }
        if (kb >= 2 * qb) {
            int cbase = kb * 64 + 2 * l3;
#pragma unroll
            for (int nt = 0; nt < 8; nt++) {
                int c0 = cbase + nt * 8, c1 = c0 + 1;
                if (c0 > r0g) s[nt][0] = -1e30f;
                if (c1 > r0g) s[nt][1] = -1e30f;
                if (c0 > r1g) s[nt][2] = -1e30f;
                if (c1 > r1g) s[nt][3] = -1e30f;
            }
        }

        float mx0 = -1e30f, mx1 = -1e30f;
#pragma unroll
        for (int nt = 0; nt < 8; nt++) {
            mx0 = fmaxf(mx0, fmaxf(s[nt][0], s[nt][1]));
            mx1 = fmaxf(mx1, fmaxf(s[nt][2], s[nt][3]));
        }
        mx0 = fmaxf(mx0, __shfl_xor_sync(0xffffffffu, mx0, 1));
        mx0 = fmaxf(mx0, __shfl_xor_sync(0xffffffffu, mx0, 2));
        mx1 = fmaxf(mx1, __shfl_xor_sync(0xffffffffu, mx1, 1));
        mx1 = fmaxf(mx1, __shfl_xor_sync(0xffffffffu, mx1, 2));
        float mn0 = fmaxf(m0, mx0), mn1 = fmaxf(m1, mx1);
        float al0 = __expf(m0 - mn0), al1 = __expf(m1 - mn1);
        m0 = mn0; m1 = mn1;
        float rs0 = 0.f, rs1 = 0.f;
#pragma unroll
        for (int nt = 0; nt < 8; nt++) {
            s[nt][0] = __expf(s[nt][0] - mn0); rs0 += s[nt][0];
            s[nt][1] = __expf(s[nt][1] - mn0); rs0 += s[nt][1];
            s[nt][2] = __expf(s[nt][2] - mn1); rs1 += s[nt][2];
            s[nt][3] = __expf(s[nt][3] - mn1); rs1 += s[nt][3];
        }
        rs0 += __shfl_xor_sync(0xffffffffu, rs0, 1);
        rs0 += __shfl_xor_sync(0xffffffffu, rs0, 2);
        rs1 += __shfl_xor_sync(0xffffffffu, rs1, 1);
        rs1 += __shfl_xor_sync(0xffffffffu, rs1, 2);
        l0 = l0 * al0 + rs0;
        l1 = l1 * al1 + rs1;
#pragma unroll
        for (int nt = 0; nt < 16; nt++) {
            o[nt][0] *= al0; o[nt][1] *= al0;
            o[nt][2] *= al1; o[nt][3] *= al1;
        }

        // ---- O += P V (2-term: P residual dropped)
#pragma unroll
        for (int j = 0; j < 4; j++) {
            uint32_t phi[4];
            phi[0] = pack_h2(s[2 * j][0],     s[2 * j][1]);
            phi[1] = pack_h2(s[2 * j][2],     s[2 * j][3]);
            phi[2] = pack_h2(s[2 * j + 1][0], s[2 * j + 1][1]);
            phi[3] = pack_h2(s[2 * j + 1][2], s[2 * j + 1][3]);
            int vrow = j * 16 + ((mat & 1) << 3) + l7;
#pragma unroll
            for (int nb = 0; nb < 8; nb++) {
                uint32_t v_hi[4], v_lo[4];
                int vch = nb * 2 + (mat >> 1);
                uint32_t vaddr = Vb + (uint32_t)(vrow * 256 + ((vch ^ (vrow & 7)) << 4));
                ldsm_x4t(v_hi, vaddr);
                ldsm_x4t(v_lo, vaddr + 16384);
#pragma unroll
                for (int e = 0; e < 2; e++) {
                    int nt = nb * 2 + e;
                    mma16816(o[nt], phi, v_hi[e * 2], v_hi[e * 2 + 1]);
                    mma16816(o[nt], phi, v_lo[e * 2], v_lo[e * 2 + 1]);
                }
            }
        }
        __syncthreads();
    }

    float inv0 = 1.f / l0, inv1 = 1.f / l1;
    size_t ro0 = (size_t)r0g * NHD + h * HD + 2 * l3;
    size_t ro1 = (size_t)r1g * NHD + h * HD + 2 * l3;
#pragma unroll
    for (int nt = 0; nt < 16; nt++) {
        *(uint32_t*)(Ahi + ro0 + nt * 8) = pack_h2(o[nt][0] * inv0, o[nt][1] * inv0);
        *(uint32_t*)(Ahi + ro1 + nt * 8) = pack_h2(o[nt][2] * inv1, o[nt][3] * inv1);
    }
}

// ---------------- launcher ---------------------------------------------------
extern "C" void kernel_launch(void* const* d_in, const int* in_sizes, int n_in,
                              void* d_out, int out_size) {
    const float* x     = (const float*)d_in[0];
    const int*   amask = (const int*)  d_in[1];
    const int*   pos   = (const int*)  d_in[2];
    const float* Wq    = (const float*)d_in[3];
    const float* Wk    = (const float*)d_in[4];
    const float* Wv    = (const float*)d_in[5];
    const float* Wo    = (const float*)d_in[6];
    float* out = (float*)d_out;

    float *qp, *kp, *vp;
    cudaGetSymbolAddress((void**)&qp, g_q);
    cudaGetSymbolAddress((void**)&kp, g_k);
    cudaGetSymbolAddress((void**)&vp, g_v);
    __half *xh, *xl, *wqh, *wql, *wkh, *wkl, *wvh, *wvl, *woh, *ah;
    __half *qhi, *qlo, *khiT, *kloT, *vhi, *vlo;
    cudaGetSymbolAddress((void**)&xh,  g_x_hi);  cudaGetSymbolAddress((void**)&xl,  g_x_lo);
    cudaGetSymbolAddress((void**)&wqh, g_wq_hi); cudaGetSymbolAddress((void**)&wql, g_wq_lo);
    cudaGetSymbolAddress((void**)&wkh, g_wk_hi); cudaGetSymbolAddress((void**)&wkl, g_wk_lo);
    cudaGetSymbolAddress((void**)&wvh, g_wv_hi); cudaGetSymbolAddress((void**)&wvl, g_wv_lo);
    cudaGetSymbolAddress((void**)&woh, g_wo_hi);
    cudaGetSymbolAddress((void**)&ah,  g_a_hi);
    cudaGetSymbolAddress((void**)&qhi, g_qhi);   cudaGetSymbolAddress((void**)&qlo, g_qlo);
    cudaGetSymbolAddress((void**)&khiT, g_khiT); cudaGetSymbolAddress((void**)&kloT, g_kloT);
    cudaGetSymbolAddress((void**)&vhi, g_vhi);   cudaGetSymbolAddress((void**)&vlo, g_vlo);

    // 0) fused split of x + weights (Wo truncated only)
    const int SPLIT_TOT = (S_LEN * HID + HID * NH * HD + 2 * HID * NKV * HD
                           + NH * HD * HID) / 4;
    split_all_kernel<<<(SPLIT_TOT + 255) / 256, 256>>>(
        x, Wq, Wk, Wv, Wo, xh, xl, wqh, wql, wkh, wkl, wvh, wvl, woh);

    // 1) RoPE table
    build_rope_kernel<<<(S_LEN * 64 + 255) / 256, 256>>>(pos);

    // 2) fused QKV projection (HMMA 3-term, R7 config)
    const int gemm_smem = 98304;
    cudaFuncSetAttribute(gemm_hmma_kernel<1, 1, 1>,
                         cudaFuncAttributeMaxDynamicSharedMemorySize, gemm_smem);
    cudaFuncSetAttribute(gemm_hmma_kernel<0, 0, 0>,
                         cudaFuncAttributeMaxDynamicSharedMemorySize, gemm_smem);
    gemm_hmma_kernel<1, 1, 1><<<dim3(36, 16), 256, gemm_smem>>>(
        xh, xl, wqh, wql, wkh, wkl, wvh, wvl, qp, kp, vp, HID, NH * HD);

    // 3) fused RoPE+split (Q, K^T) + V split
    const int PREP_TOT = S_LEN * NH * 64 + S_LEN * NKV * 64 + S_LEN * NKV * HD / 4;
    prep_attention_kernel<<<(PREP_TOT + 255) / 256, 256>>>(
        qp, kp, vp, qhi, qlo, khiT, kloT, vhi, vlo);

    // 4) HMMA flash attention (3-term QK, 2-term PV) -> fp16 hi output
    const int flash_smem = 196864;
    cudaFuncSetAttribute(flash_hmma_kernel,
                         cudaFuncAttributeMaxDynamicSharedMemorySize, flash_smem);
    flash_hmma_kernel<<<dim3(S_LEN / 128, NH), 256, flash_smem>>>(
        qhi, qlo, khiT, kloT, vhi, vlo, amask, ah);

    // 5) O projection (HMMA, 1-term pure fp16) -> final output
    gemm_hmma_kernel<0, 0, 0><<<dim3(28, 16), 256, gemm_smem>>>(
        ah, nullptr, woh, nullptr, nullptr, nullptr, nullptr, nullptr,
        out, nullptr, nullptr, HID, HID);
}

// round 11
// speedup vs baseline: 1.2217x; 1.0277x over previous
#include <cuda_runtime.h>
#include <cuda_fp16.h>
#include <math.h>
#include <cstdint>

#define S_LEN 2048
#define HID   3584
#define NH    28
#define NKV   4
#define HD    128
#define REP   7
#define NHD   (NH * HD)
#define QK_SCALE 0.0883883476483184406f

// ---------------- scratch (device globals; no allocations allowed) ----------
__device__ float g_q[S_LEN * NH * HD];
__device__ float g_k[S_LEN * NKV * HD];
__device__ float g_sin[S_LEN * 64];
__device__ float g_cos[S_LEN * 64];

__device__ __align__(16) __half g_x_hi[S_LEN * HID];
__device__ __align__(16) __half g_x_lo[S_LEN * HID];
__device__ __align__(16) __half g_wq_hi[HID * NH * HD];
__device__ __align__(16) __half g_wq_lo[HID * NH * HD];
__device__ __align__(16) __half g_wk_hi[HID * NKV * HD];
__device__ __align__(16) __half g_wk_lo[HID * NKV * HD];
__device__ __align__(16) __half g_wv_hi[HID * NKV * HD];
__device__ __align__(16) __half g_wv_lo[HID * NKV * HD];
__device__ __align__(16) __half g_wo_hi[NH * HD * HID];
__device__ __align__(16) __half g_a_hi[S_LEN * NH * HD];
// flash operands
__device__ __align__(16) __half g_qhi[S_LEN * NH * HD];
__device__ __align__(16) __half g_qlo[S_LEN * NH * HD];
__device__ __align__(16) __half g_khiT[NKV * HD * S_LEN];   // [NKV][HD][S]
__device__ __align__(16) __half g_kloT[NKV * HD * S_LEN];
__device__ __align__(16) __half g_vhi[S_LEN * NKV * HD];
__device__ __align__(16) __half g_vlo[S_LEN * NKV * HD];

// ---------------- HMMA helpers (base-target instructions only) --------------
__device__ __forceinline__ uint32_t smem_u32(const void* p) {
    uint32_t a;
    asm("{ .reg .u64 t; cvta.to.shared.u64 t, %1; cvt.u32.u64 %0, t; }"
        : "=r"(a) : "l"(p));
    return a;
}
__device__ __forceinline__ void ldsm_x4(uint32_t* r, uint32_t addr) {
    asm volatile("ldmatrix.sync.aligned.m8n8.x4.shared.b16 {%0,%1,%2,%3}, [%4];"
        : "=r"(r[0]), "=r"(r[1]), "=r"(r[2]), "=r"(r[3]) : "r"(addr));
}
__device__ __forceinline__ void ldsm_x4t(uint32_t* r, uint32_t addr) {
    asm volatile("ldmatrix.sync.aligned.m8n8.x4.trans.shared.b16 {%0,%1,%2,%3}, [%4];"
        : "=r"(r[0]), "=r"(r[1]), "=r"(r[2]), "=r"(r[3]) : "r"(addr));
}
__device__ __forceinline__ void mma16816(float* d, const uint32_t* a,
                                         uint32_t b0, uint32_t b1) {
    asm volatile(
        "mma.sync.aligned.m16n8k16.row.col.f32.f16.f16.f32 "
        "{%0,%1,%2,%3}, {%4,%5,%6,%7}, {%8,%9}, {%0,%1,%2,%3};"
        : "+f"(d[0]), "+f"(d[1]), "+f"(d[2]), "+f"(d[3])
        : "r"(a[0]), "r"(a[1]), "r"(a[2]), "r"(a[3]), "r"(b0), "r"(b1));
}
#define CPASYNC16(dst, src) \
    asm volatile("cp.async.cg.shared.global [%0], [%1], 16;" \
                 :: "r"(dst), "l"(src) : "memory")
#define CP_COMMIT() asm volatile("cp.async.commit_group;" ::: "memory")
#define CP_WAIT1()  asm volatile("cp.async.wait_group 1;" ::: "memory")
#define CP_WAIT0()  asm volatile("cp.async.wait_group 0;" ::: "memory")

// pack two floats -> fp16x2 in a u32
__device__ __forceinline__ uint32_t pack_h2(float x, float y) {
    __half hx = __float2half_rn(x), hy = __float2half_rn(y);
    return (uint32_t)__half_as_ushort(hx) | ((uint32_t)__half_as_ushort(hy) << 16);
}
// split two floats into (hi pair, lo pair) u32s
__device__ __forceinline__ void split2_u32(float x, float y,
                                           uint32_t& hi, uint32_t& lo) {
    __half hx = __float2half_rn(x), hy = __float2half_rn(y);
    float rx = x - __half2float(hx), ry = y - __half2float(hy);
    hi = (uint32_t)__half_as_ushort(hx) | ((uint32_t)__half_as_ushort(hy) << 16);
    lo = (uint32_t)__half_as_ushort(__float2half_rn(rx))
       | ((uint32_t)__half_as_ushort(__float2half_rn(ry)) << 16);
}

__device__ __forceinline__ void split4_at(const float* __restrict__ src,
                                          __half* __restrict__ hi,
                                          __half* __restrict__ lo, int i) {
    float4 v = ((const float4*)src)[i];
    uint32_t h0, l0, h1, l1;
    split2_u32(v.x, v.y, h0, l0);
    split2_u32(v.z, v.w, h1, l1);
    ((uint2*)hi)[i] = make_uint2(h0, h1);
    ((uint2*)lo)[i] = make_uint2(l0, l1);
}
__device__ __forceinline__ void trunc4_at(const float* __restrict__ src,
                                          __half* __restrict__ hi, int i) {
    float4 v = ((const float4*)src)[i];
    ((uint2*)hi)[i] = make_uint2(pack_h2(v.x, v.y), pack_h2(v.z, v.w));
}

// ---------------- fused split of x + weights (Wo: hi only) -------------------
__global__ void split_all_kernel(const float* __restrict__ x,
                                 const float* __restrict__ wq,
                                 const float* __restrict__ wk,
                                 const float* __restrict__ wv,
                                 const float* __restrict__ wo,
                                 __half* xh, __half* xl, __half* qh, __half* ql,
                                 __half* kh, __half* kl, __half* vh, __half* vl,
                                 __half* oh) {
    const int C0 = S_LEN * HID / 4;
    const int C1 = C0 + HID * NH * HD / 4;
    const int C2 = C1 + HID * NKV * HD / 4;
    const int C3 = C2 + HID * NKV * HD / 4;
    const int C4 = C3 + NH * HD * HID / 4;
    int i = blockIdx.x * blockDim.x + threadIdx.x;
    if (i >= C4) return;
    if (i < C0)      split4_at(x,  xh, xl, i);
    else if (i < C1) split4_at(wq, qh, ql, i - C0);
    else if (i < C2) split4_at(wk, kh, kl, i - C1);
    else if (i < C3) split4_at(wv, vh, vl, i - C2);
    else             trunc4_at(wo, oh, i - C3);
}

// ---------------- RoPE sin/cos table -----------------------------------------
__global__ void build_rope_kernel(const int* __restrict__ pos) {
    int idx = blockIdx.x * blockDim.x + threadIdx.x;
    if (idx >= S_LEN * 64) return;
    int i = idx & 63;
    int s = idx >> 6;
    double inv = exp(-((double)i / 64.0) * log(1.0e6));
    double ang = (double)pos[s] * inv;
    g_sin[idx] = (float)sin(ang);
    g_cos[idx] = (float)cos(ang);
}

// ---------------- fused: RoPE+split Q | RoPE+split K^T (V handled in GEMM) ---
__global__ void prep_attention_kernel(const float* __restrict__ Q,
                                      const float* __restrict__ Kc,
                                      __half* __restrict__ qhi, __half* __restrict__ qlo,
                                      __half* __restrict__ khiT, __half* __restrict__ kloT) {
    const int R0 = S_LEN * NH * 64;
    const int R1 = R0 + S_LEN * NKV * 64;
    int idx = blockIdx.x * blockDim.x + threadIdx.x;
    if (idx >= R1) return;

    if (idx < R0) {
        int i = idx & 63;
        int t = idx >> 6;
        int h = t % NH;
        int s = t / NH;
        float sn = g_sin[s * 64 + i], cs = g_cos[s * 64 + i];
        const float* p = Q + ((size_t)s * NH + h) * HD;
        float x0 = p[i], x1 = p[i + 64];
        float y0 = (x0 * cs - x1 * sn) * QK_SCALE;
        float y1 = (x1 * cs + x0 * sn) * QK_SCALE;
        size_t o = ((size_t)s * NH + h) * HD;
        __half h0 = __float2half_rn(y0);
        qhi[o + i] = h0;
        qlo[o + i] = __float2half_rn(y0 - __half2float(h0));
        __half h1 = __float2half_rn(y1);
        qhi[o + i + 64] = h1;
        qlo[o + i + 64] = __float2half_rn(y1 - __half2float(h1));
    } else {
        int j = idx - R0;
        int s = j & (S_LEN - 1);
        int t = j >> 11;
        int i = t & 63;
        int kvh = t >> 6;
        float sn = g_sin[s * 64 + i], cs = g_cos[s * 64 + i];
        const float* p = Kc + ((size_t)s * NKV + kvh) * HD;
        float x0 = p[i], x1 = p[i + 64];
        float y0 = x0 * cs - x1 * sn;
        float y1 = x1 * cs + x0 * sn;
        size_t o0 = ((size_t)kvh * HD + i) * S_LEN + s;
        size_t o1 = ((size_t)kvh * HD + i + 64) * S_LEN + s;
        __half h0 = __float2half_rn(y0);
        khiT[o0] = h0;
        kloT[o0] = __float2half_rn(y0 - __half2float(h0));
        __half h1 = __float2half_rn(y1);
        khiT[o1] = h1;
        kloT[o1] = __float2half_rn(y1 - __half2float(h1));
    }
}

// ---------------- HMMA GEMM: 128x128 tile, 3-stage pipeline, forced occ 2 ----
// BK=32, 8 warps (2M x 4N), warp tile 64x32. Stage 32KB.
// ALO adds a_lo*b_hi; BLO adds a_hi*b_lo. QKV: <1,1,1>. O-proj: <0,0,0>.
// FUSED: V block-columns (bn>=32) write fp16 hi/lo split directly (Vh/Vl).
template <int FUSED, int ALO, int BLO>
__global__ __launch_bounds__(256, 2)
void gemm_hmma_kernel(const __half* __restrict__ Ahi, const __half* __restrict__ Alo,
                      const __half* __restrict__ Bhi0, const __half* __restrict__ Blo0,
                      const __half* __restrict__ Bhi1, const __half* __restrict__ Blo1,
                      const __half* __restrict__ Bhi2, const __half* __restrict__ Blo2,
                      float* __restrict__ C0, float* __restrict__ C1,
                      __half* __restrict__ Vh, __half* __restrict__ Vl,
                      int K, int N0) {
    extern __shared__ char smem[];
    uint32_t sb = smem_u32(smem);
    // stage = 32KB: A_hi[0,8K) A_lo[8K,16K) B_hi[16K,24K) B_lo[24K,32K); 3 stages

    int tid = threadIdx.x, wid = tid >> 5, lane = tid & 31;
    int bn = blockIdx.x, bm = blockIdx.y;
    int wm = wid & 1, wn = wid >> 1;

    const __half* Bhi = Bhi0;
    const __half* Blo = Blo0;
    float* C = C0;
    int ldn = N0, bcol = bn * 128;
    bool is_v = false;
    if (FUSED) {
        if (bn >= 28 && bn < 32) {
            Bhi = Bhi1; Blo = Blo1; C = C1; ldn = NKV * HD; bcol = (bn - 28) * 128;
        } else if (bn >= 32) {
            Bhi = Bhi2; Blo = Blo2; ldn = NKV * HD; bcol = (bn - 32) * 128;
            is_v = true;
        }
    }

    int ar0 = tid >> 2, ac0 = tid & 3;
    int ar1 = (tid + 256) >> 2, ac1 = tid & 3;
    int br0 = tid >> 4, bc0 = tid & 15;
    int br1 = (tid + 256) >> 4, bc1 = tid & 15;
    uint32_t a_d0 = (uint32_t)(ar0 * 64 + ((ac0 ^ ((ar0 >> 1) & 3)) << 4));
    uint32_t a_d1 = (uint32_t)(ar1 * 64 + ((ac1 ^ ((ar1 >> 1) & 3)) << 4));
    uint32_t b_d0 = (uint32_t)(br0 * 256 + ((bc0 ^ (br0 & 7)) << 4));
    uint32_t b_d1 = (uint32_t)(br1 * 256 + ((bc1 ^ (br1 & 7)) << 4));

    const int nch = K >> 5;

#define LOAD_STAGE(stg, ch) do {                                              \
    uint32_t base = sb + (uint32_t)(stg) * 32768u;                            \
    const __half* ah = Ahi + (size_t)(bm * 128) * K + (ch) * 32;              \
    CPASYNC16(base + a_d0, ah + (size_t)ar0 * K + ac0 * 8);                   \
    CPASYNC16(base + a_d1, ah + (size_t)ar1 * K + ac1 * 8);                   \
    if (ALO) {                                                                \
        const __half* al = Alo + (size_t)(bm * 128) * K + (ch) * 32;          \
        CPASYNC16(base + 8192 + a_d0, al + (size_t)ar0 * K + ac0 * 8);        \
        CPASYNC16(base + 8192 + a_d1, al + (size_t)ar1 * K + ac1 * 8);        \
    }                                                                         \
    const __half* bh = Bhi + (size_t)((ch) * 32) * ldn + bcol;                \
    CPASYNC16(base + 16384 + b_d0, bh + (size_t)br0 * ldn + bc0 * 8);         \
    CPASYNC16(base + 16384 + b_d1, bh + (size_t)br1 * ldn + bc1 * 8);         \
    if (BLO) {                                                                \
        const __half* bl = Blo + (size_t)((ch) * 32) * ldn + bcol;            \
        CPASYNC16(base + 24576 + b_d0, bl + (size_t)br0 * ldn + bc0 * 8);     \
        CPASYNC16(base + 24576 + b_d1, bl + (size_t)br1 * ldn + bc1 * 8);     \
    }                                                                         \
} while (0)

    int mat = lane >> 3;
    int arb = wm * 64 + ((mat & 1) << 3) + (lane & 7);
    int asw = (arb >> 1) & 3;
    int bkb = ((mat & 1) << 3) + (lane & 7);
    int bsw = lane & 7;
    int bnc = wn * 4 + (mat >> 1);

    float acc[4][4][4];
#pragma unroll
    for (int i = 0; i < 4; i++)
#pragma unroll
        for (int j = 0; j < 4; j++)
#pragma unroll
            for (int q = 0; q < 4; q++) acc[i][j][q] = 0.f;

    LOAD_STAGE(0, 0);
    CP_COMMIT();
    if (nch > 1) {
        LOAD_STAGE(1, 1);
        CP_COMMIT();
    }

    int stg = 0;
    for (int ch = 0; ch < nch; ch++) {
        if (ch + 1 < nch) { CP_WAIT1(); } else { CP_WAIT0(); }
        __syncthreads();
        if (ch + 2 < nch) {
            int ns = stg + 2;
            if (ns >= 3) ns -= 3;
            LOAD_STAGE(ns, ch + 2);
            CP_COMMIT();
        }

        uint32_t Ab_hi = sb + (uint32_t)stg * 32768u;
        uint32_t Ab_lo = Ab_hi + 8192;
        uint32_t Bb_hi = Ab_hi + 16384;
        uint32_t Bb_lo = Ab_hi + 24576;

#pragma unroll
        for (int kh = 0; kh < 2; kh++) {
            uint32_t ac = (uint32_t)(((kh * 2 + (mat >> 1)) ^ asw) << 4);
            uint32_t a_hi[4][4], a_lo[4][4];
#pragma unroll
            for (int mt = 0; mt < 4; mt++) {
                uint32_t ro = (uint32_t)((arb + mt * 16) * 64);
                ldsm_x4(a_hi[mt], Ab_hi + ro + ac);
                if (ALO) ldsm_x4(a_lo[mt], Ab_lo + ro + ac);
            }
            uint32_t bro = (uint32_t)((kh * 16 + bkb) * 256);
            uint32_t b_hi[2][4], b_lo[2][4];
#pragma unroll
            for (int p = 0; p < 2; p++) {
                uint32_t co = (uint32_t)((((bnc + p * 2)) ^ bsw) << 4);
                ldsm_x4t(b_hi[p], Bb_hi + bro + co);
                if (BLO) ldsm_x4t(b_lo[p], Bb_lo + bro + co);
            }
#pragma unroll
            for (int mt = 0; mt < 4; mt++)
#pragma unroll
                for (int p = 0; p < 2; p++) {
                    mma16816(acc[mt][p * 2],     a_hi[mt], b_hi[p][0], b_hi[p][1]);
                    mma16816(acc[mt][p * 2 + 1], a_hi[mt], b_hi[p][2], b_hi[p][3]);
                    if (BLO) {
                        mma16816(acc[mt][p * 2],     a_hi[mt], b_lo[p][0], b_lo[p][1]);
                        mma16816(acc[mt][p * 2 + 1], a_hi[mt], b_lo[p][2], b_lo[p][3]);
                    }
                    if (ALO) {
                        mma16816(acc[mt][p * 2],     a_lo[mt], b_hi[p][0], b_hi[p][1]);
                        mma16816(acc[mt][p * 2 + 1], a_lo[mt], b_hi[p][2], b_hi[p][3]);
                    }
                }
        }
        if (++stg == 3) stg = 0;
    }
#undef LOAD_STAGE

    if (FUSED && is_v) {
        // V epilogue: write fp16 hi/lo split directly
#pragma unroll
        for (int mt = 0; mt < 4; mt++) {
            int row = bm * 128 + wm * 64 + mt * 16 + (lane >> 2);
#pragma unroll
            for (int nt = 0; nt < 4; nt++) {
                int col = bcol + wn * 32 + (nt >> 1) * 16 + (nt & 1) * 8 + (lane & 3) * 2;
                uint32_t h0, l0, h1, l1;
                split2_u32(acc[mt][nt][0], acc[mt][nt][1], h0, l0);
                split2_u32(acc[mt][nt][2], acc[mt][nt][3], h1, l1);
                *(uint32_t*)(Vh + (size_t)row * ldn + col) = h0;
                *(uint32_t*)(Vl + (size_t)row * ldn + col) = l0;
                *(uint32_t*)(Vh + (size_t)(row + 8) * ldn + col) = h1;
                *(uint32_t*)(Vl + (size_t)(row + 8) * ldn + col) = l1;
            }
        }
    } else {
#pragma unroll
        for (int mt = 0; mt < 4; mt++) {
            int row = bm * 128 + wm * 64 + mt * 16 + (lane >> 2);
#pragma unroll
            for (int nt = 0; nt < 4; nt++) {
                int col = bcol + wn * 32 + (nt >> 1) * 16 + (nt & 1) * 8 + (lane & 3) * 2;
                *(float2*)(C + (size_t)row * ldn + col) =
                    make_float2(acc[mt][nt][0], acc[mt][nt][1]);
                *(float2*)(C + (size_t)(row + 8) * ldn + col) =
                    make_float2(acc[mt][nt][2], acc[mt][nt][3]);
            }
        }
    }
}

// ---------------- HMMA flash attention: 3-term QK, 2-term PV ----------------
__global__ __launch_bounds__(256, 1)
void flash_hmma_kernel(const __half* __restrict__ Qhi, const __half* __restrict__ Qlo,
                       const __half* __restrict__ KhiT, const __half* __restrict__ KloT,
                       const __half* __restrict__ Vhi, const __half* __restrict__ Vlo,
                       const int* __restrict__ amask,
                       __half* __restrict__ Ahi) {
    extern __shared__ char sm[];
    uint32_t sb = smem_u32(sm);
    float* sbias = (float*)(sm + 196608);

    int tid = threadIdx.x, wq = tid >> 5, lane = tid & 31;
    int mat = lane >> 3, l7 = lane & 7, qd = lane >> 2, l3 = lane & 3;
    int qb = (int)(gridDim.x - 1 - blockIdx.x);
    int h = blockIdx.y, kvh = h / REP;

    {
        const __half* qh = Qhi + ((size_t)(qb * 128) * NH + h) * HD;
        const __half* ql = Qlo + ((size_t)(qb * 128) * NH + h) * HD;
#pragma unroll
        for (int i = 0; i < 8; i++) {
            int idx = tid + i * 256;
            int row = idx >> 4, ch = idx & 15;
            uint32_t dst = sb + (uint32_t)(row * 256 + ((ch ^ (row & 7)) << 4));
            CPASYNC16(dst,         qh + (size_t)row * NHD + ch * 8);
            CPASYNC16(dst + 32768, ql + (size_t)row * NHD + ch * 8);
        }
    }

    auto load_kv = [&](int stage, int kb) {
        uint32_t base = sb + 65536u + (uint32_t)stage * 65536u;
        const __half* kh_ = KhiT + (size_t)kvh * HD * S_LEN + kb * 64;
        const __half* kl_ = KloT + (size_t)kvh * HD * S_LEN + kb * 64;
#pragma unroll
        for (int i = 0; i < 4; i++) {
            int idx = tid + i * 256;
            int row = idx >> 3, ch = idx & 7;
            uint32_t dst = base + (uint32_t)(row * 128 + ((ch ^ (row & 7)) << 4));
            CPASYNC16(dst,         kh_ + (size_t)row * S_LEN + ch * 8);
            CPASYNC16(dst + 16384, kl_ + (size_t)row * S_LEN + ch * 8);
        }
        const __half* vh_ = Vhi + ((size_t)(kb * 64) * NKV + kvh) * HD;
        const __half* vl_ = Vlo + ((size_t)(kb * 64) * NKV + kvh) * HD;
#pragma unroll
        for (int i = 0; i < 4; i++) {
            int idx = tid + i * 256;
            int row = idx >> 4, ch = idx & 15;
            uint32_t dst = base + 32768u + (uint32_t)(row * 256 + ((ch ^ (row & 7)) << 4));
            CPASYNC16(dst,         vh_ + (size_t)row * NKV * HD + ch * 8);
            CPASYNC16(dst + 16384, vl_ + (size_t)row * NKV * HD + ch * 8);
        }
    };

    load_kv(0, 0);
    CP_COMMIT();

    float o[16][4];
#pragma unroll
    for (int i = 0; i < 16; i++)
#pragma unroll
        for (int j = 0; j < 4; j++) o[i][j] = 0.f;
    float m0 = -1e30f, m1 = -1e30f, l0 = 0.f, l1 = 0.f;

    int kbmax = 2 * qb + 1;
    int r0g = qb * 128 + wq * 16 + qd, r1g = r0g + 8;
    int arow = wq * 16 + ((mat & 1) << 3) + l7;
    int brow0 = ((mat & 1) << 3) + l7;

    for (int kb = 0; kb <= kbmax; kb++) {
        if (kb < kbmax) {
            load_kv((kb + 1) & 1, kb + 1);
            CP_COMMIT();
            CP_WAIT1();
        } else {
            CP_WAIT0();
        }
        if (tid < 64) sbias[tid] = amask[kb * 64 + tid] ? 0.f : -1e30f;
        __syncthreads();

        uint32_t Kb = sb + 65536u + (uint32_t)(kb & 1) * 65536u;
        uint32_t Vb = Kb + 32768u;

        float s[8][4];
#pragma unroll
        for (int i = 0; i < 8; i++)
#pragma unroll
            for (int j = 0; j < 4; j++) s[i][j] = 0.f;

#pragma unroll
        for (int kh2 = 0; kh2 < 8; kh2++) {
            uint32_t a_hi[4], a_lo[4];
            int ach = kh2 * 2 + (mat >> 1);
            uint32_t aaddr = sb + (uint32_t)(arow * 256 + ((ach ^ (arow & 7)) << 4));
            ldsm_x4(a_hi, aaddr);
            ldsm_x4(a_lo, aaddr + 32768);
            int brow = kh2 * 16 + brow0;
#pragma unroll
            for (int hf = 0; hf < 2; hf++) {
                uint32_t b_hi[2][4], b_lo[2][4];
#pragma unroll
                for (int p = 0; p < 2; p++) {
                    int bch = (hf * 2 + p) * 2 + (mat >> 1);
                    uint32_t baddr = Kb + (uint32_t)(brow * 128 + ((bch ^ (brow & 7)) << 4));
                    ldsm_x4t(b_hi[p], baddr);
                    ldsm_x4t(b_lo[p], baddr + 16384);
                }
#pragma unroll
                for (int p = 0; p < 2; p++)
#pragma unroll
                    for (int e = 0; e < 2; e++) {
                        int nt = hf * 4 + p * 2 + e;
                        mma16816(s[nt], a_hi, b_hi[p][e * 2], b_hi[p][e * 2 + 1]);
                        mma16816(s[nt], a_hi, b_lo[p][e * 2], b_lo[p][e * 2 + 1]);
                        mma16816(s[nt], a_lo, b_hi[p][e * 2], b_hi[p][e * 2 + 1]);
                    }
            }
        }

#pragma unroll
        for (int nt = 0; nt < 8; nt++) {
            int c = nt * 8 + 2 * l3;
            float b0 = sbias[c], b1 = sbias[c + 1];
            s[nt][0] += b0; s[nt][1] += b1; s[nt][2] += b0; s[nt][3] += b1;
        }
        if (kb >= 2 * qb) {
            int cbase = kb * 64 + 2 * l3;
#pragma unroll
            for (int nt = 0; nt < 8; nt++) {
                int c0 = cbase + nt * 8, c1 = c0 + 1;
                if (c0 > r0g) s[nt][0] = -1e30f;
                if (c1 > r0g) s[nt][1] = -1e30f;
                if (c0 > r1g) s[nt][2] = -1e30f;
                if (c1 > r1g) s[nt][3] = -1e30f;
            }
        }

        float mx0 = -1e30f, mx1 = -1e30f;
#pragma unroll
        for (int nt = 0; nt < 8; nt++) {
            mx0 = fmaxf(mx0, fmaxf(s[nt][0], s[nt][1]));
            mx1 = fmaxf(mx1, fmaxf(s[nt][2], s[nt][3]));
        }
        mx0 = fmaxf(mx0, __shfl_xor_sync(0xffffffffu, mx0, 1));
        mx0 = fmaxf(mx0, __shfl_xor_sync(0xffffffffu, mx0, 2));
        mx1 = fmaxf(mx1, __shfl_xor_sync(0xffffffffu, mx1, 1));
        mx1 = fmaxf(mx1, __shfl_xor_sync(0xffffffffu, mx1, 2));
        float mn0 = fmaxf(m0, mx0), mn1 = fmaxf(m1, mx1);
        float al0 = __expf(m0 - mn0), al1 = __expf(m1 - mn1);
        m0 = mn0; m1 = mn1;
        float rs0 = 0.f, rs1 = 0.f;
#pragma unroll
        for (int nt = 0; nt < 8; nt++) {
            s[nt][0] = __expf(s[nt][0] - mn0); rs0 += s[nt][0];
            s[nt][1] = __expf(s[nt][1] - mn0); rs0 += s[nt][1];
            s[nt][2] = __expf(s[nt][2] - mn1); rs1 += s[nt][2];
            s[nt][3] = __expf(s[nt][3] - mn1); rs1 += s[nt][3];
        }
        rs0 += __shfl_xor_sync(0xffffffffu, rs0, 1);
        rs0 += __shfl_xor_sync(0xffffffffu, rs0, 2);
        rs1 += __shfl_xor_sync(0xffffffffu, rs1, 1);
        rs1 += __shfl_xor_sync(0xffffffffu, rs1, 2);
        l0 = l0 * al0 + rs0;
        l1 = l1 * al1 + rs1;
#pragma unroll
        for (int nt = 0; nt < 16; nt++) {
            o[nt][0] *= al0; o[nt][1] *= al0;
            o[nt][2] *= al1; o[nt][3] *= al1;
        }

        // ---- O += P V (2-term: P residual dropped)
#pragma unroll
        for (int j = 0; j < 4; j++) {
            uint32_t phi[4];
            phi[0] = pack_h2(s[2 * j][0],     s[2 * j][1]);
            phi[1] = pack_h2(s[2 * j][2],     s[2 * j][3]);
            phi[2] = pack_h2(s[2 * j + 1][0], s[2 * j + 1][1]);
            phi[3] = pack_h2(s[2 * j + 1][2], s[2 * j + 1][3]);
            int vrow = j * 16 + ((mat & 1) << 3) + l7;
#pragma unroll
            for (int nb = 0; nb < 8; nb++) {
                uint32_t v_hi[4], v_lo[4];
                int vch = nb * 2 + (mat >> 1);
                uint32_t vaddr = Vb + (uint32_t)(vrow * 256 + ((vch ^ (vrow & 7)) << 4));
                ldsm_x4t(v_hi, vaddr);
                ldsm_x4t(v_lo, vaddr + 16384);
#pragma unroll
                for (int e = 0; e < 2; e++) {
                    int nt = nb * 2 + e;
                    mma16816(o[nt], phi, v_hi[e * 2], v_hi[e * 2 + 1]);
                    mma16816(o[nt], phi, v_lo[e * 2], v_lo[e * 2 + 1]);
                }
            }
        }
        __syncthreads();
    }

    float inv0 = 1.f / l0, inv1 = 1.f / l1;
    size_t ro0 = (size_t)r0g * NHD + h * HD + 2 * l3;
    size_t ro1 = (size_t)r1g * NHD + h * HD + 2 * l3;
#pragma unroll
    for (int nt = 0; nt < 16; nt++) {
        *(uint32_t*)(Ahi + ro0 + nt * 8) = pack_h2(o[nt][0] * inv0, o[nt][1] * inv0);
        *(uint32_t*)(Ahi + ro1 + nt * 8) = pack_h2(o[nt][2] * inv1, o[nt][3] * inv1);
    }
}

// ---------------- launcher ---------------------------------------------------
extern "C" void kernel_launch(void* const* d_in, const int* in_sizes, int n_in,
                              void* d_out, int out_size) {
    const float* x     = (const float*)d_in[0];
    const int*   amask = (const int*)  d_in[1];
    const int*   pos   = (const int*)  d_in[2];
    const float* Wq    = (const float*)d_in[3];
    const float* Wk    = (const float*)d_in[4];
    const float* Wv    = (const float*)d_in[5];
    const float* Wo    = (const float*)d_in[6];
    float* out = (float*)d_out;

    float *qp, *kp;
    cudaGetSymbolAddress((void**)&qp, g_q);
    cudaGetSymbolAddress((void**)&kp, g_k);
    __half *xh, *xl, *wqh, *wql, *wkh, *wkl, *wvh, *wvl, *woh, *ah;
    __half *qhi, *qlo, *khiT, *kloT, *vhi, *vlo;
    cudaGetSymbolAddress((void**)&xh,  g_x_hi);  cudaGetSymbolAddress((void**)&xl,  g_x_lo);
    cudaGetSymbolAddress((void**)&wqh, g_wq_hi); cudaGetSymbolAddress((void**)&wql, g_wq_lo);
    cudaGetSymbolAddress((void**)&wkh, g_wk_hi); cudaGetSymbolAddress((void**)&wkl, g_wk_lo);
    cudaGetSymbolAddress((void**)&wvh, g_wv_hi); cudaGetSymbolAddress((void**)&wvl, g_wv_lo);
    cudaGetSymbolAddress((void**)&woh, g_wo_hi);
    cudaGetSymbolAddress((void**)&ah,  g_a_hi);
    cudaGetSymbolAddress((void**)&qhi, g_qhi);   cudaGetSymbolAddress((void**)&qlo, g_qlo);
    cudaGetSymbolAddress((void**)&khiT, g_khiT); cudaGetSymbolAddress((void**)&kloT, g_kloT);
    cudaGetSymbolAddress((void**)&vhi, g_vhi);   cudaGetSymbolAddress((void**)&vlo, g_vlo);

    // 0) fused split of x + weights (Wo truncated only)
    const int SPLIT_TOT = (S_LEN * HID + HID * NH * HD + 2 * HID * NKV * HD
                           + NH * HD * HID) / 4;
    split_all_kernel<<<(SPLIT_TOT + 255) / 256, 256>>>(
        x, Wq, Wk, Wv, Wo, xh, xl, wqh, wql, wkh, wkl, wvh, wvl, woh);

    // 1) RoPE table
    build_rope_kernel<<<(S_LEN * 64 + 255) / 256, 256>>>(pos);

    // 2) fused QKV projection (HMMA 3-term; V written as fp16 split in-epilogue)
    const int gemm_smem = 98304;
    cudaFuncSetAttribute(gemm_hmma_kernel<1, 1, 1>,
                         cudaFuncAttributeMaxDynamicSharedMemorySize, gemm_smem);
    cudaFuncSetAttribute(gemm_hmma_kernel<0, 0, 0>,
                         cudaFuncAttributeMaxDynamicSharedMemorySize, gemm_smem);
    gemm_hmma_kernel<1, 1, 1><<<dim3(36, 16), 256, gemm_smem>>>(
        xh, xl, wqh, wql, wkh, wkl, wvh, wvl, qp, kp, vhi, vlo, HID, NH * HD);

    // 3) fused RoPE+split (Q, K^T)
    const int PREP_TOT = S_LEN * NH * 64 + S_LEN * NKV * 64;
    prep_attention_kernel<<<(PREP_TOT + 255) / 256, 256>>>(
        qp, kp, qhi, qlo, khiT, kloT);

    // 4) HMMA flash attention (3-term QK, 2-term PV) -> fp16 hi output
    const int flash_smem = 196864;
    cudaFuncSetAttribute(flash_hmma_kernel,
                         cudaFuncAttributeMaxDynamicSharedMemorySize, flash_smem);
    flash_hmma_kernel<<<dim3(S_LEN / 128, NH), 256, flash_smem>>>(
        qhi, qlo, khiT, kloT, vhi, vlo, amask, ah);

    // 5) O projection (HMMA, 1-term pure fp16) -> final output
    gemm_hmma_kernel<0, 0, 0><<<dim3(28, 16), 256, gemm_smem>>>(
        ah, nullptr, woh, nullptr, nullptr, nullptr, nullptr, nullptr,
        out, nullptr, nullptr, nullptr, HID, HID);
}

// round 12
// speedup vs baseline: 1.7629x; 1.4430x over previous
#include <cuda_runtime.h>
#include <cuda_fp16.h>
#include <math.h>
#include <cstdint>

#define S_LEN 2048
#define HID   3584
#define NH    28
#define NKV   4
#define HD    128
#define REP   7
#define NHD   (NH * HD)
#define QK_SCALE 0.0883883476483184406f

// ---------------- scratch (device globals; no allocations allowed) ----------
__device__ float g_q[S_LEN * NH * HD];
__device__ float g_k[S_LEN * NKV * HD];
__device__ float g_sin[S_LEN * 64];
__device__ float g_cos[S_LEN * 64];

__device__ __align__(16) __half g_x_hi[S_LEN * HID];
__device__ __align__(16) __half g_wq_hi[HID * NH * HD];
__device__ __align__(16) __half g_wk_hi[HID * NKV * HD];
__device__ __align__(16) __half g_wv_hi[HID * NKV * HD];
__device__ __align__(16) __half g_wo_hi[NH * HD * HID];
__device__ __align__(16) __half g_a_hi[S_LEN * NH * HD];
// flash operands
__device__ __align__(16) __half g_qhi[S_LEN * NH * HD];
__device__ __align__(16) __half g_qlo[S_LEN * NH * HD];
__device__ __align__(16) __half g_khiT[NKV * HD * S_LEN];   // [NKV][HD][S]
__device__ __align__(16) __half g_kloT[NKV * HD * S_LEN];
__device__ __align__(16) __half g_vhi[S_LEN * NKV * HD];
__device__ __align__(16) __half g_vlo[S_LEN * NKV * HD];

// ---------------- HMMA helpers (base-target instructions only) --------------
__device__ __forceinline__ uint32_t smem_u32(const void* p) {
    uint32_t a;
    asm("{ .reg .u64 t; cvta.to.shared.u64 t, %1; cvt.u32.u64 %0, t; }"
        : "=r"(a) : "l"(p));
    return a;
}
__device__ __forceinline__ void ldsm_x4(uint32_t* r, uint32_t addr) {
    asm volatile("ldmatrix.sync.aligned.m8n8.x4.shared.b16 {%0,%1,%2,%3}, [%4];"
        : "=r"(r[0]), "=r"(r[1]), "=r"(r[2]), "=r"(r[3]) : "r"(addr));
}
__device__ __forceinline__ void ldsm_x4t(uint32_t* r, uint32_t addr) {
    asm volatile("ldmatrix.sync.aligned.m8n8.x4.trans.shared.b16 {%0,%1,%2,%3}, [%4];"
        : "=r"(r[0]), "=r"(r[1]), "=r"(r[2]), "=r"(r[3]) : "r"(addr));
}
__device__ __forceinline__ void mma16816(float* d, const uint32_t* a,
                                         uint32_t b0, uint32_t b1) {
    asm volatile(
        "mma.sync.aligned.m16n8k16.row.col.f32.f16.f16.f32 "
        "{%0,%1,%2,%3}, {%4,%5,%6,%7}, {%8,%9}, {%0,%1,%2,%3};"
        : "+f"(d[0]), "+f"(d[1]), "+f"(d[2]), "+f"(d[3])
        : "r"(a[0]), "r"(a[1]), "r"(a[2]), "r"(a[3]), "r"(b0), "r"(b1));
}
#define CPASYNC16(dst, src) \
    asm volatile("cp.async.cg.shared.global [%0], [%1], 16;" \
                 :: "r"(dst), "l"(src) : "memory")
#define CP_COMMIT() asm volatile("cp.async.commit_group;" ::: "memory")
#define CP_WAIT1()  asm volatile("cp.async.wait_group 1;" ::: "memory")
#define CP_WAIT0()  asm volatile("cp.async.wait_group 0;" ::: "memory")

// pack two floats -> fp16x2 in a u32
__device__ __forceinline__ uint32_t pack_h2(float x, float y) {
    __half hx = __float2half_rn(x), hy = __float2half_rn(y);
    return (uint32_t)__half_as_ushort(hx) | ((uint32_t)__half_as_ushort(hy) << 16);
}
// split two floats into (hi pair, lo pair) u32s
__device__ __forceinline__ void split2_u32(float x, float y,
                                           uint32_t& hi, uint32_t& lo) {
    __half hx = __float2half_rn(x), hy = __float2half_rn(y);
    float rx = x - __half2float(hx), ry = y - __half2float(hy);
    hi = (uint32_t)__half_as_ushort(hx) | ((uint32_t)__half_as_ushort(hy) << 16);
    lo = (uint32_t)__half_as_ushort(__float2half_rn(rx))
       | ((uint32_t)__half_as_ushort(__float2half_rn(ry)) << 16);
}
__device__ __forceinline__ void trunc4_at(const float* __restrict__ src,
                                          __half* __restrict__ hi, int i) {
    float4 v = ((const float4*)src)[i];
    ((uint2*)hi)[i] = make_uint2(pack_h2(v.x, v.y), pack_h2(v.z, v.w));
}

// ---------------- fused truncation of x + all weights to fp16 ----------------
__global__ void split_all_kernel(const float* __restrict__ x,
                                 const float* __restrict__ wq,
                                 const float* __restrict__ wk,
                                 const float* __restrict__ wv,
                                 const float* __restrict__ wo,
                                 __half* xh, __half* qh, __half* kh,
                                 __half* vh, __half* oh) {
    const int C0 = S_LEN * HID / 4;
    const int C1 = C0 + HID * NH * HD / 4;
    const int C2 = C1 + HID * NKV * HD / 4;
    const int C3 = C2 + HID * NKV * HD / 4;
    const int C4 = C3 + NH * HD * HID / 4;
    int i = blockIdx.x * blockDim.x + threadIdx.x;
    if (i >= C4) return;
    if (i < C0)      trunc4_at(x,  xh, i);
    else if (i < C1) trunc4_at(wq, qh, i - C0);
    else if (i < C2) trunc4_at(wk, kh, i - C1);
    else if (i < C3) trunc4_at(wv, vh, i - C2);
    else             trunc4_at(wo, oh, i - C3);
}

// ---------------- RoPE sin/cos table -----------------------------------------
__global__ void build_rope_kernel(const int* __restrict__ pos) {
    int idx = blockIdx.x * blockDim.x + threadIdx.x;
    if (idx >= S_LEN * 64) return;
    int i = idx & 63;
    int s = idx >> 6;
    double inv = exp(-((double)i / 64.0) * log(1.0e6));
    double ang = (double)pos[s] * inv;
    g_sin[idx] = (float)sin(ang);
    g_cos[idx] = (float)cos(ang);
}

// ---------------- fused: RoPE+split Q | RoPE+split K^T -----------------------
__global__ void prep_attention_kernel(const float* __restrict__ Q,
                                      const float* __restrict__ Kc,
                                      __half* __restrict__ qhi, __half* __restrict__ qlo,
                                      __half* __restrict__ khiT, __half* __restrict__ kloT) {
    const int R0 = S_LEN * NH * 64;
    const int R1 = R0 + S_LEN * NKV * 64;
    int idx = blockIdx.x * blockDim.x + threadIdx.x;
    if (idx >= R1) return;

    if (idx < R0) {
        int i = idx & 63;
        int t = idx >> 6;
        int h = t % NH;
        int s = t / NH;
        float sn = g_sin[s * 64 + i], cs = g_cos[s * 64 + i];
        const float* p = Q + ((size_t)s * NH + h) * HD;
        float x0 = p[i], x1 = p[i + 64];
        float y0 = (x0 * cs - x1 * sn) * QK_SCALE;
        float y1 = (x1 * cs + x0 * sn) * QK_SCALE;
        size_t o = ((size_t)s * NH + h) * HD;
        __half h0 = __float2half_rn(y0);
        qhi[o + i] = h0;
        qlo[o + i] = __float2half_rn(y0 - __half2float(h0));
        __half h1 = __float2half_rn(y1);
        qhi[o + i + 64] = h1;
        qlo[o + i + 64] = __float2half_rn(y1 - __half2float(h1));
    } else {
        int j = idx - R0;
        int s = j & (S_LEN - 1);
        int t = j >> 11;
        int i = t & 63;
        int kvh = t >> 6;
        float sn = g_sin[s * 64 + i], cs = g_cos[s * 64 + i];
        const float* p = Kc + ((size_t)s * NKV + kvh) * HD;
        float x0 = p[i], x1 = p[i + 64];
        float y0 = x0 * cs - x1 * sn;
        float y1 = x1 * cs + x0 * sn;
        size_t o0 = ((size_t)kvh * HD + i) * S_LEN + s;
        size_t o1 = ((size_t)kvh * HD + i + 64) * S_LEN + s;
        __half h0 = __float2half_rn(y0);
        khiT[o0] = h0;
        kloT[o0] = __float2half_rn(y0 - __half2float(h0));
        __half h1 = __float2half_rn(y1);
        khiT[o1] = h1;
        kloT[o1] = __float2half_rn(y1 - __half2float(h1));
    }
}

// ---------------- HMMA GEMM: 128x128 tile, 3-stage pipeline (pure fp16) ------
// BK=32, 8 warps (2M x 4N), warp tile 64x32. Stage 16KB (A_hi 8K + B_hi 8K).
// FUSED: QKV column-block select (28 Q | 4 K | 4 V); V writes fp16 hi/lo split.
template <int FUSED>
__global__ __launch_bounds__(256, 2)
void gemm_hmma_kernel(const __half* __restrict__ Ahi,
                      const __half* __restrict__ Bhi0,
                      const __half* __restrict__ Bhi1,
                      const __half* __restrict__ Bhi2,
                      float* __restrict__ C0, float* __restrict__ C1,
                      __half* __restrict__ Vh, __half* __restrict__ Vl,
                      int K, int N0) {
    extern __shared__ char smem[];
    uint32_t sb = smem_u32(smem);
    // stage = 16KB: A_hi[0,8K) B_hi[8K,16K); 3 stages

    int tid = threadIdx.x, wid = tid >> 5, lane = tid & 31;
    int bn = blockIdx.x, bm = blockIdx.y;
    int wm = wid & 1, wn = wid >> 1;

    const __half* Bhi = Bhi0;
    float* C = C0;
    int ldn = N0, bcol = bn * 128;
    bool is_v = false;
    if (FUSED) {
        if (bn >= 28 && bn < 32) {
            Bhi = Bhi1; C = C1; ldn = NKV * HD; bcol = (bn - 28) * 128;
        } else if (bn >= 32) {
            Bhi = Bhi2; ldn = NKV * HD; bcol = (bn - 32) * 128;
            is_v = true;
        }
    }

    int ar0 = tid >> 2, ac0 = tid & 3;
    int ar1 = (tid + 256) >> 2, ac1 = tid & 3;
    int br0 = tid >> 4, bc0 = tid & 15;
    int br1 = (tid + 256) >> 4, bc1 = tid & 15;
    uint32_t a_d0 = (uint32_t)(ar0 * 64 + ((ac0 ^ ((ar0 >> 1) & 3)) << 4));
    uint32_t a_d1 = (uint32_t)(ar1 * 64 + ((ac1 ^ ((ar1 >> 1) & 3)) << 4));
    uint32_t b_d0 = (uint32_t)(br0 * 256 + ((bc0 ^ (br0 & 7)) << 4));
    uint32_t b_d1 = (uint32_t)(br1 * 256 + ((bc1 ^ (br1 & 7)) << 4));

    const int nch = K >> 5;

#define LOAD_STAGE(stg, ch) do {                                              \
    uint32_t base = sb + (uint32_t)(stg) * 16384u;                            \
    const __half* ah = Ahi + (size_t)(bm * 128) * K + (ch) * 32;              \
    CPASYNC16(base + a_d0, ah + (size_t)ar0 * K + ac0 * 8);                   \
    CPASYNC16(base + a_d1, ah + (size_t)ar1 * K + ac1 * 8);                   \
    const __half* bh = Bhi + (size_t)((ch) * 32) * ldn + bcol;                \
    CPASYNC16(base + 8192 + b_d0, bh + (size_t)br0 * ldn + bc0 * 8);          \
    CPASYNC16(base + 8192 + b_d1, bh + (size_t)br1 * ldn + bc1 * 8);          \
} while (0)

    int mat = lane >> 3;
    int arb = wm * 64 + ((mat & 1) << 3) + (lane & 7);
    int asw = (arb >> 1) & 3;
    int bkb = ((mat & 1) << 3) + (lane & 7);
    int bsw = lane & 7;
    int bnc = wn * 4 + (mat >> 1);

    float acc[4][4][4];
#pragma unroll
    for (int i = 0; i < 4; i++)
#pragma unroll
        for (int j = 0; j < 4; j++)
#pragma unroll
            for (int q = 0; q < 4; q++) acc[i][j][q] = 0.f;

    LOAD_STAGE(0, 0);
    CP_COMMIT();
    if (nch > 1) {
        LOAD_STAGE(1, 1);
        CP_COMMIT();
    }

    int stg = 0;
    for (int ch = 0; ch < nch; ch++) {
        if (ch + 1 < nch) { CP_WAIT1(); } else { CP_WAIT0(); }
        __syncthreads();
        if (ch + 2 < nch) {
            int ns = stg + 2;
            if (ns >= 3) ns -= 3;
            LOAD_STAGE(ns, ch + 2);
            CP_COMMIT();
        }

        uint32_t Ab_hi = sb + (uint32_t)stg * 16384u;
        uint32_t Bb_hi = Ab_hi + 8192;

#pragma unroll
        for (int kh = 0; kh < 2; kh++) {
            uint32_t ac = (uint32_t)(((kh * 2 + (mat >> 1)) ^ asw) << 4);
            uint32_t a_hi[4][4];
#pragma unroll
            for (int mt = 0; mt < 4; mt++) {
                uint32_t ro = (uint32_t)((arb + mt * 16) * 64);
                ldsm_x4(a_hi[mt], Ab_hi + ro + ac);
            }
            uint32_t bro = (uint32_t)((kh * 16 + bkb) * 256);
            uint32_t b_hi[2][4];
#pragma unroll
            for (int p = 0; p < 2; p++) {
                uint32_t co = (uint32_t)((((bnc + p * 2)) ^ bsw) << 4);
                ldsm_x4t(b_hi[p], Bb_hi + bro + co);
            }
#pragma unroll
            for (int mt = 0; mt < 4; mt++)
#pragma unroll
                for (int p = 0; p < 2; p++) {
                    mma16816(acc[mt][p * 2],     a_hi[mt], b_hi[p][0], b_hi[p][1]);
                    mma16816(acc[mt][p * 2 + 1], a_hi[mt], b_hi[p][2], b_hi[p][3]);
                }
        }
        if (++stg == 3) stg = 0;
    }
#undef LOAD_STAGE

    if (FUSED && is_v) {
        // V epilogue: write fp16 hi/lo split directly
#pragma unroll
        for (int mt = 0; mt < 4; mt++) {
            int row = bm * 128 + wm * 64 + mt * 16 + (lane >> 2);
#pragma unroll
            for (int nt = 0; nt < 4; nt++) {
                int col = bcol + wn * 32 + (nt >> 1) * 16 + (nt & 1) * 8 + (lane & 3) * 2;
                uint32_t h0, l0, h1, l1;
                split2_u32(acc[mt][nt][0], acc[mt][nt][1], h0, l0);
                split2_u32(acc[mt][nt][2], acc[mt][nt][3], h1, l1);
                *(uint32_t*)(Vh + (size_t)row * ldn + col) = h0;
                *(uint32_t*)(Vl + (size_t)row * ldn + col) = l0;
                *(uint32_t*)(Vh + (size_t)(row + 8) * ldn + col) = h1;
                *(uint32_t*)(Vl + (size_t)(row + 8) * ldn + col) = l1;
            }
        }
    } else {
#pragma unroll
        for (int mt = 0; mt < 4; mt++) {
            int row = bm * 128 + wm * 64 + mt * 16 + (lane >> 2);
#pragma unroll
            for (int nt = 0; nt < 4; nt++) {
                int col = bcol + wn * 32 + (nt >> 1) * 16 + (nt & 1) * 8 + (lane & 3) * 2;
                *(float2*)(C + (size_t)row * ldn + col) =
                    make_float2(acc[mt][nt][0], acc[mt][nt][1]);
                *(float2*)(C + (size_t)(row + 8) * ldn + col) =
                    make_float2(acc[mt][nt][2], acc[mt][nt][3]);
            }
        }
    }
}

// ---------------- HMMA flash attention: 3-term QK, 2-term PV ----------------
__global__ __launch_bounds__(256, 1)
void flash_hmma_kernel(const __half* __restrict__ Qhi, const __half* __restrict__ Qlo,
                       const __half* __restrict__ KhiT, const __half* __restrict__ KloT,
                       const __half* __restrict__ Vhi, const __half* __restrict__ Vlo,
                       const int* __restrict__ amask,
                       __half* __restrict__ Ahi) {
    extern __shared__ char sm[];
    uint32_t sb = smem_u32(sm);
    float* sbias = (float*)(sm + 196608);

    int tid = threadIdx.x, wq = tid >> 5, lane = tid & 31;
    int mat = lane >> 3, l7 = lane & 7, qd = lane >> 2, l3 = lane & 3;
    int qb = (int)(gridDim.x - 1 - blockIdx.x);
    int h = blockIdx.y, kvh = h / REP;

    {
        const __half* qh = Qhi + ((size_t)(qb * 128) * NH + h) * HD;
        const __half* ql = Qlo + ((size_t)(qb * 128) * NH + h) * HD;
#pragma unroll
        for (int i = 0; i < 8; i++) {
            int idx = tid + i * 256;
            int row = idx >> 4, ch = idx & 15;
            uint32_t dst = sb + (uint32_t)(row * 256 + ((ch ^ (row & 7)) << 4));
            CPASYNC16(dst,         qh + (size_t)row * NHD + ch * 8);
            CPASYNC16(dst + 32768, ql + (size_t)row * NHD + ch * 8);
        }
    }

    auto load_kv = [&](int stage, int kb) {
        uint32_t base = sb + 65536u + (uint32_t)stage * 65536u;
        const __half* kh_ = KhiT + (size_t)kvh * HD * S_LEN + kb * 64;
        const __half* kl_ = KloT + (size_t)kvh * HD * S_LEN + kb * 64;
#pragma unroll
        for (int i = 0; i < 4; i++) {
            int idx = tid + i * 256;
            int row = idx >> 3, ch = idx & 7;
            uint32_t dst = base + (uint32_t)(row * 128 + ((ch ^ (row & 7)) << 4));
            CPASYNC16(dst,         kh_ + (size_t)row * S_LEN + ch * 8);
            CPASYNC16(dst + 16384, kl_ + (size_t)row * S_LEN + ch * 8);
        }
        const __half* vh_ = Vhi + ((size_t)(kb * 64) * NKV + kvh) * HD;
        const __half* vl_ = Vlo + ((size_t)(kb * 64) * NKV + kvh) * HD;
#pragma unroll
        for (int i = 0; i < 4; i++) {
            int idx = tid + i * 256;
            int row = idx >> 4, ch = idx & 15;
            uint32_t dst = base + 32768u + (uint32_t)(row * 256 + ((ch ^ (row & 7)) << 4));
            CPASYNC16(dst,         vh_ + (size_t)row * NKV * HD + ch * 8);
            CPASYNC16(dst + 16384, vl_ + (size_t)row * NKV * HD + ch * 8);
        }
    };

    load_kv(0, 0);
    CP_COMMIT();

    float o[16][4];
#pragma unroll
    for (int i = 0; i < 16; i++)
#pragma unroll
        for (int j = 0; j < 4; j++) o[i][j] = 0.f;
    float m0 = -1e30f, m1 = -1e30f, l0 = 0.f, l1 = 0.f;

    int kbmax = 2 * qb + 1;
    int r0g = qb * 128 + wq * 16 + qd, r1g = r0g + 8;
    int arow = wq * 16 + ((mat & 1) << 3) + l7;
    int brow0 = ((mat & 1) << 3) + l7;

    for (int kb = 0; kb <= kbmax; kb++) {
        if (kb < kbmax) {
            load_kv((kb + 1) & 1, kb + 1);
            CP_COMMIT();
            CP_WAIT1();
        } else {
            CP_WAIT0();
        }
        if (tid < 64) sbias[tid] = amask[kb * 64 + tid] ? 0.f : -1e30f;
        __syncthreads();

        uint32_t Kb = sb + 65536u + (uint32_t)(kb & 1) * 65536u;
        uint32_t Vb = Kb + 32768u;

        float s[8][4];
#pragma unroll
        for (int i = 0; i < 8; i++)
#pragma unroll
            for (int j = 0; j < 4; j++) s[i][j] = 0.f;

#pragma unroll
        for (int kh2 = 0; kh2 < 8; kh2++) {
            uint32_t a_hi[4], a_lo[4];
            int ach = kh2 * 2 + (mat >> 1);
            uint32_t aaddr = sb + (uint32_t)(arow * 256 + ((ach ^ (arow & 7)) << 4));
            ldsm_x4(a_hi, aaddr);
            ldsm_x4(a_lo, aaddr + 32768);
            int brow = kh2 * 16 + brow0;
#pragma unroll
            for (int hf = 0; hf < 2; hf++) {
                uint32_t b_hi[2][4], b_lo[2][4];
#pragma unroll
                for (int p = 0; p < 2; p++) {
                    int bch = (hf * 2 + p) * 2 + (mat >> 1);
                    uint32_t baddr = Kb + (uint32_t)(brow * 128 + ((bch ^ (brow & 7)) << 4));
                    ldsm_x4t(b_hi[p], baddr);
                    ldsm_x4t(b_lo[p], baddr + 16384);
                }
#pragma unroll
                for (int p = 0; p < 2; p++)
#pragma unroll
                    for (int e = 0; e < 2; e++) {
                        int nt = hf * 4 + p * 2 + e;
                        mma16816(s[nt], a_hi, b_hi[p][e * 2], b_hi[p][e * 2 + 1]);
                        mma16816(s[nt], a_hi, b_lo[p][e * 2], b_lo[p][e * 2 + 1]);
                        mma16816(s[nt], a_lo, b_hi[p][e * 2], b_hi[p][e * 2 + 1]);
                    }
            }
        }

#pragma unroll
        for (int nt = 0; nt < 8; nt++) {
            int c = nt * 8 + 2 * l3;
            float b0 = sbias[c], b1 = sbias[c + 1];
            s[nt][0] += b0; s[nt][1] += b1; s[nt][2] += b0; s[nt][3] += b1;
        }
        if (kb >= 2 * qb) {
            int cbase = kb * 64 + 2 * l3;
#pragma unroll
            for (int nt = 0; nt < 8; nt++) {
                int c0 = cbase + nt * 8, c1 = c0 + 1;
                if (c0 > r0g) s[nt][0] = -1e30f;
                if (c1 > r0g) s[nt][1] = -1e30f;
                if (c0 > r1g) s[nt][2] = -1e30f;
                if (c1 > r1g) s[nt][3] = -1e30f;
            }
        }

        float mx0 = -1e30f, mx1 = -1e30f;
#pragma unroll
        for (int nt = 0; nt < 8; nt++) {
            mx0 = fmaxf(mx0, fmaxf(s[nt][0], s[nt][1]));
            mx1 = fmaxf(mx1, fmaxf(s[nt][2], s[nt][3]));
        }
        mx0 = fmaxf(mx0, __shfl_xor_sync(0xffffffffu, mx0, 1));
        mx0 = fmaxf(mx0, __shfl_xor_sync(0xffffffffu, mx0, 2));
        mx1 = fmaxf(mx1, __shfl_xor_sync(0xffffffffu, mx1, 1));
        mx1 = fmaxf(mx1, __shfl_xor_sync(0xffffffffu, mx1, 2));
        float mn0 = fmaxf(m0, mx0), mn1 = fmaxf(m1, mx1);
        float al0 = __expf(m0 - mn0), al1 = __expf(m1 - mn1);
        m0 = mn0; m1 = mn1;
        float rs0 = 0.f, rs1 = 0.f;
#pragma unroll
        for (int nt = 0; nt < 8; nt++) {
            s[nt][0] = __expf(s[nt][0] - mn0); rs0 += s[nt][0];
            s[nt][1] = __expf(s[nt][1] - mn0); rs0 += s[nt][1];
            s[nt][2] = __expf(s[nt][2] - mn1); rs1 += s[nt][2];
            s[nt][3] = __expf(s[nt][3] - mn1); rs1 += s[nt][3];
        }
        rs0 += __shfl_xor_sync(0xffffffffu, rs0, 1);
        rs0 += __shfl_xor_sync(0xffffffffu, rs0, 2);
        rs1 += __shfl_xor_sync(0xffffffffu, rs1, 1);
        rs1 += __shfl_xor_sync(0xffffffffu, rs1, 2);
        l0 = l0 * al0 + rs0;
        l1 = l1 * al1 + rs1;
#pragma unroll
        for (int nt = 0; nt < 16; nt++) {
            o[nt][0] *= al0; o[nt][1] *= al0;
            o[nt][2] *= al1; o[nt][3] *= al1;
        }

        // ---- O += P V (2-term: P residual dropped)
#pragma unroll
        for (int j = 0; j < 4; j++) {
            uint32_t phi[4];
            phi[0] = pack_h2(s[2 * j][0],     s[2 * j][1]);
            phi[1] = pack_h2(s[2 * j][2],     s[2 * j][3]);
            phi[2] = pack_h2(s[2 * j + 1][0], s[2 * j + 1][1]);
            phi[3] = pack_h2(s[2 * j + 1][2], s[2 * j + 1][3]);
            int vrow = j * 16 + ((mat & 1) << 3) + l7;
#pragma unroll
            for (int nb = 0; nb < 8; nb++) {
                uint32_t v_hi[4], v_lo[4];
                int vch = nb * 2 + (mat >> 1);
                uint32_t vaddr = Vb + (uint32_t)(vrow * 256 + ((vch ^ (vrow & 7)) << 4));
                ldsm_x4t(v_hi, vaddr);
                ldsm_x4t(v_lo, vaddr + 16384);
#pragma unroll
                for (int e = 0; e < 2; e++) {
                    int nt = nb * 2 + e;
                    mma16816(o[nt], phi, v_hi[e * 2], v_hi[e * 2 + 1]);
                    mma16816(o[nt], phi, v_lo[e * 2], v_lo[e * 2 + 1]);
                }
            }
        }
        __syncthreads();
    }

    float inv0 = 1.f / l0, inv1 = 1.f / l1;
    size_t ro0 = (size_t)r0g * NHD + h * HD + 2 * l3;
    size_t ro1 = (size_t)r1g * NHD + h * HD + 2 * l3;
#pragma unroll
    for (int nt = 0; nt < 16; nt++) {
        *(uint32_t*)(Ahi + ro0 + nt * 8) = pack_h2(o[nt][0] * inv0, o[nt][1] * inv0);
        *(uint32_t*)(Ahi + ro1 + nt * 8) = pack_h2(o[nt][2] * inv1, o[nt][3] * inv1);
    }
}

// ---------------- launcher ---------------------------------------------------
extern "C" void kernel_launch(void* const* d_in, const int* in_sizes, int n_in,
                              void* d_out, int out_size) {
    const float* x     = (const float*)d_in[0];
    const int*   amask = (const int*)  d_in[1];
    const int*   pos   = (const int*)  d_in[2];
    const float* Wq    = (const float*)d_in[3];
    const float* Wk    = (const float*)d_in[4];
    const float* Wv    = (const float*)d_in[5];
    const float* Wo    = (const float*)d_in[6];
    float* out = (float*)d_out;

    float *qp, *kp;
    cudaGetSymbolAddress((void**)&qp, g_q);
    cudaGetSymbolAddress((void**)&kp, g_k);
    __half *xh, *wqh, *wkh, *wvh, *woh, *ah;
    __half *qhi, *qlo, *khiT, *kloT, *vhi, *vlo;
    cudaGetSymbolAddress((void**)&xh,  g_x_hi);
    cudaGetSymbolAddress((void**)&wqh, g_wq_hi);
    cudaGetSymbolAddress((void**)&wkh, g_wk_hi);
    cudaGetSymbolAddress((void**)&wvh, g_wv_hi);
    cudaGetSymbolAddress((void**)&woh, g_wo_hi);
    cudaGetSymbolAddress((void**)&ah,  g_a_hi);
    cudaGetSymbolAddress((void**)&qhi, g_qhi);   cudaGetSymbolAddress((void**)&qlo, g_qlo);
    cudaGetSymbolAddress((void**)&khiT, g_khiT); cudaGetSymbolAddress((void**)&kloT, g_kloT);
    cudaGetSymbolAddress((void**)&vhi, g_vhi);   cudaGetSymbolAddress((void**)&vlo, g_vlo);

    // 0) fused fp16 truncation of x + all weights
    const int SPLIT_TOT = (S_LEN * HID + HID * NH * HD + 2 * HID * NKV * HD
                           + NH * HD * HID) / 4;
    split_all_kernel<<<(SPLIT_TOT + 255) / 256, 256>>>(
        x, Wq, Wk, Wv, Wo, xh, wqh, wkh, wvh, woh);

    // 1) RoPE table
    build_rope_kernel<<<(S_LEN * 64 + 255) / 256, 256>>>(pos);

    // 2) fused QKV projection (HMMA, pure fp16; V written as fp16 split)
    const int gemm_smem = 49152;
    cudaFuncSetAttribute(gemm_hmma_kernel<1>,
                         cudaFuncAttributeMaxDynamicSharedMemorySize, gemm_smem);
    cudaFuncSetAttribute(gemm_hmma_kernel<0>,
                         cudaFuncAttributeMaxDynamicSharedMemorySize, gemm_smem);
    gemm_hmma_kernel<1><<<dim3(36, 16), 256, gemm_smem>>>(
        xh, wqh, wkh, wvh, qp, kp, vhi, vlo, HID, NH * HD);

    // 3) fused RoPE+split (Q, K^T)
    const int PREP_TOT = S_LEN * NH * 64 + S_LEN * NKV * 64;
    prep_attention_kernel<<<(PREP_TOT + 255) / 256, 256>>>(
        qp, kp, qhi, qlo, khiT, kloT);

    // 4) HMMA flash attention (3-term QK, 2-term PV) -> fp16 hi output
    const int flash_smem = 196864;
    cudaFuncSetAttribute(flash_hmma_kernel,
                         cudaFuncAttributeMaxDynamicSharedMemorySize, flash_smem);
    flash_hmma_kernel<<<dim3(S_LEN / 128, NH), 256, flash_smem>>>(
        qhi, qlo, khiT, kloT, vhi, vlo, amask, ah);

    // 5) O projection (HMMA, pure fp16) -> final output
    gemm_hmma_kernel<0><<<dim3(28, 16), 256, gemm_smem>>>(
        ah, woh, nullptr, nullptr, out, nullptr, nullptr, nullptr, HID, HID);
}

// round 13
// speedup vs baseline: 1.8513x; 1.0502x over previous
#include <cuda_runtime.h>
#include <cuda_fp16.h>
#include <math.h>
#include <cstdint>

#define S_LEN 2048
#define HID   3584
#define NH    28
#define NKV   4
#define HD    128
#define REP   7
#define NHD   (NH * HD)
#define QK_SCALE 0.0883883476483184406f

// ---------------- scratch (device globals; no allocations allowed) ----------
__device__ float g_q[S_LEN * NH * HD];
__device__ float g_k[S_LEN * NKV * HD];
__device__ float g_sin[S_LEN * 64];
__device__ float g_cos[S_LEN * 64];

__device__ __align__(16) __half g_x_hi[S_LEN * HID];
__device__ __align__(16) __half g_wq_hi[HID * NH * HD];
__device__ __align__(16) __half g_wk_hi[HID * NKV * HD];
__device__ __align__(16) __half g_wv_hi[HID * NKV * HD];
__device__ __align__(16) __half g_wo_hi[NH * HD * HID];
__device__ __align__(16) __half g_a_hi[S_LEN * NH * HD];
// flash operands
__device__ __align__(16) __half g_qhi[S_LEN * NH * HD];
__device__ __align__(16) __half g_qlo[S_LEN * NH * HD];
__device__ __align__(16) __half g_khiT[NKV * HD * S_LEN];   // [NKV][HD][S]
__device__ __align__(16) __half g_kloT[NKV * HD * S_LEN];
__device__ __align__(16) __half g_vhi[S_LEN * NKV * HD];

// ---------------- HMMA helpers (base-target instructions only) --------------
__device__ __forceinline__ uint32_t smem_u32(const void* p) {
    uint32_t a;
    asm("{ .reg .u64 t; cvta.to.shared.u64 t, %1; cvt.u32.u64 %0, t; }"
        : "=r"(a) : "l"(p));
    return a;
}
__device__ __forceinline__ void ldsm_x4(uint32_t* r, uint32_t addr) {
    asm volatile("ldmatrix.sync.aligned.m8n8.x4.shared.b16 {%0,%1,%2,%3}, [%4];"
        : "=r"(r[0]), "=r"(r[1]), "=r"(r[2]), "=r"(r[3]) : "r"(addr));
}
__device__ __forceinline__ void ldsm_x4t(uint32_t* r, uint32_t addr) {
    asm volatile("ldmatrix.sync.aligned.m8n8.x4.trans.shared.b16 {%0,%1,%2,%3}, [%4];"
        : "=r"(r[0]), "=r"(r[1]), "=r"(r[2]), "=r"(r[3]) : "r"(addr));
}
__device__ __forceinline__ void mma16816(float* d, const uint32_t* a,
                                         uint32_t b0, uint32_t b1) {
    asm volatile(
        "mma.sync.aligned.m16n8k16.row.col.f32.f16.f16.f32 "
        "{%0,%1,%2,%3}, {%4,%5,%6,%7}, {%8,%9}, {%0,%1,%2,%3};"
        : "+f"(d[0]), "+f"(d[1]), "+f"(d[2]), "+f"(d[3])
        : "r"(a[0]), "r"(a[1]), "r"(a[2]), "r"(a[3]), "r"(b0), "r"(b1));
}
#define CPASYNC16(dst, src) \
    asm volatile("cp.async.cg.shared.global [%0], [%1], 16;" \
                 :: "r"(dst), "l"(src) : "memory")
#define CP_COMMIT() asm volatile("cp.async.commit_group;" ::: "memory")
#define CP_WAIT1()  asm volatile("cp.async.wait_group 1;" ::: "memory")
#define CP_WAIT0()  asm volatile("cp.async.wait_group 0;" ::: "memory")

// pack two floats -> fp16x2 in a u32
__device__ __forceinline__ uint32_t pack_h2(float x, float y) {
    __half hx = __float2half_rn(x), hy = __float2half_rn(y);
    return (uint32_t)__half_as_ushort(hx) | ((uint32_t)__half_as_ushort(hy) << 16);
}
__device__ __forceinline__ void trunc4_at(const float* __restrict__ src,
                                          __half* __restrict__ hi, int i) {
    float4 v = ((const float4*)src)[i];
    ((uint2*)hi)[i] = make_uint2(pack_h2(v.x, v.y), pack_h2(v.z, v.w));
}

// ---------------- fused: truncate x + weights to fp16, plus RoPE table -------
__global__ void split_all_kernel(const float* __restrict__ x,
                                 const float* __restrict__ wq,
                                 const float* __restrict__ wk,
                                 const float* __restrict__ wv,
                                 const float* __restrict__ wo,
                                 const int* __restrict__ pos,
                                 __half* xh, __half* qh, __half* kh,
                                 __half* vh, __half* oh) {
    const int C0 = S_LEN * HID / 4;
    const int C1 = C0 + HID * NH * HD / 4;
    const int C2 = C1 + HID * NKV * HD / 4;
    const int C3 = C2 + HID * NKV * HD / 4;
    const int C4 = C3 + NH * HD * HID / 4;
    const int C5 = C4 + S_LEN * 64;        // rope table entries
    int i = blockIdx.x * blockDim.x + threadIdx.x;
    if (i >= C5) return;
    if (i < C0)      trunc4_at(x,  xh, i);
    else if (i < C1) trunc4_at(wq, qh, i - C0);
    else if (i < C2) trunc4_at(wk, kh, i - C1);
    else if (i < C3) trunc4_at(wv, vh, i - C2);
    else if (i < C4) trunc4_at(wo, oh, i - C3);
    else {
        int idx = i - C4;
        int fi = idx & 63;
        int s = idx >> 6;
        double inv = exp(-((double)fi / 64.0) * log(1.0e6));
        double ang = (double)pos[s] * inv;
        g_sin[idx] = (float)sin(ang);
        g_cos[idx] = (float)cos(ang);
    }
}

// ---------------- fused: RoPE+split Q | RoPE+split K^T -----------------------
__global__ void prep_attention_kernel(const float* __restrict__ Q,
                                      const float* __restrict__ Kc,
                                      __half* __restrict__ qhi, __half* __restrict__ qlo,
                                      __half* __restrict__ khiT, __half* __restrict__ kloT) {
    const int R0 = S_LEN * NH * 64;
    const int R1 = R0 + S_LEN * NKV * 64;
    int idx = blockIdx.x * blockDim.x + threadIdx.x;
    if (idx >= R1) return;

    if (idx < R0) {
        int i = idx & 63;
        int t = idx >> 6;
        int h = t % NH;
        int s = t / NH;
        float sn = g_sin[s * 64 + i], cs = g_cos[s * 64 + i];
        const float* p = Q + ((size_t)s * NH + h) * HD;
        float x0 = p[i], x1 = p[i + 64];
        float y0 = (x0 * cs - x1 * sn) * QK_SCALE;
        float y1 = (x1 * cs + x0 * sn) * QK_SCALE;
        size_t o = ((size_t)s * NH + h) * HD;
        __half h0 = __float2half_rn(y0);
        qhi[o + i] = h0;
        qlo[o + i] = __float2half_rn(y0 - __half2float(h0));
        __half h1 = __float2half_rn(y1);
        qhi[o + i + 64] = h1;
        qlo[o + i + 64] = __float2half_rn(y1 - __half2float(h1));
    } else {
        int j = idx - R0;
        int s = j & (S_LEN - 1);
        int t = j >> 11;
        int i = t & 63;
        int kvh = t >> 6;
        float sn = g_sin[s * 64 + i], cs = g_cos[s * 64 + i];
        const float* p = Kc + ((size_t)s * NKV + kvh) * HD;
        float x0 = p[i], x1 = p[i + 64];
        float y0 = x0 * cs - x1 * sn;
        float y1 = x1 * cs + x0 * sn;
        size_t o0 = ((size_t)kvh * HD + i) * S_LEN + s;
        size_t o1 = ((size_t)kvh * HD + i + 64) * S_LEN + s;
        __half h0 = __float2half_rn(y0);
        khiT[o0] = h0;
        kloT[o0] = __float2half_rn(y0 - __half2float(h0));
        __half h1 = __float2half_rn(y1);
        khiT[o1] = h1;
        kloT[o1] = __float2half_rn(y1 - __half2float(h1));
    }
}

// ---------------- HMMA GEMM: 128x128 tile, 3-stage pipeline (pure fp16) ------
// BK=32, 8 warps (2M x 4N), warp tile 64x32. Stage 16KB (A_hi 8K + B_hi 8K).
// FUSED: QKV column-block select (28 Q | 4 K | 4 V); V writes fp16 truncated.
template <int FUSED>
__global__ __launch_bounds__(256, 2)
void gemm_hmma_kernel(const __half* __restrict__ Ahi,
                      const __half* __restrict__ Bhi0,
                      const __half* __restrict__ Bhi1,
                      const __half* __restrict__ Bhi2,
                      float* __restrict__ C0, float* __restrict__ C1,
                      __half* __restrict__ Vh,
                      int K, int N0) {
    extern __shared__ char smem[];
    uint32_t sb = smem_u32(smem);
    // stage = 16KB: A_hi[0,8K) B_hi[8K,16K); 3 stages

    int tid = threadIdx.x, wid = tid >> 5, lane = tid & 31;
    int bn = blockIdx.x, bm = blockIdx.y;
    int wm = wid & 1, wn = wid >> 1;

    const __half* Bhi = Bhi0;
    float* C = C0;
    int ldn = N0, bcol = bn * 128;
    bool is_v = false;
    if (FUSED) {
        if (bn >= 28 && bn < 32) {
            Bhi = Bhi1; C = C1; ldn = NKV * HD; bcol = (bn - 28) * 128;
        } else if (bn >= 32) {
            Bhi = Bhi2; ldn = NKV * HD; bcol = (bn - 32) * 128;
            is_v = true;
        }
    }

    int ar0 = tid >> 2, ac0 = tid & 3;
    int ar1 = (tid + 256) >> 2, ac1 = tid & 3;
    int br0 = tid >> 4, bc0 = tid & 15;
    int br1 = (tid + 256) >> 4, bc1 = tid & 15;
    uint32_t a_d0 = (uint32_t)(ar0 * 64 + ((ac0 ^ ((ar0 >> 1) & 3)) << 4));
    uint32_t a_d1 = (uint32_t)(ar1 * 64 + ((ac1 ^ ((ar1 >> 1) & 3)) << 4));
    uint32_t b_d0 = (uint32_t)(br0 * 256 + ((bc0 ^ (br0 & 7)) << 4));
    uint32_t b_d1 = (uint32_t)(br1 * 256 + ((bc1 ^ (br1 & 7)) << 4));

    const int nch = K >> 5;

#define LOAD_STAGE(stg, ch) do {                                              \
    uint32_t base = sb + (uint32_t)(stg) * 16384u;                            \
    const __half* ah = Ahi + (size_t)(bm * 128) * K + (ch) * 32;              \
    CPASYNC16(base + a_d0, ah + (size_t)ar0 * K + ac0 * 8);                   \
    CPASYNC16(base + a_d1, ah + (size_t)ar1 * K + ac1 * 8);                   \
    const __half* bh = Bhi + (size_t)((ch) * 32) * ldn + bcol;                \
    CPASYNC16(base + 8192 + b_d0, bh + (size_t)br0 * ldn + bc0 * 8);          \
    CPASYNC16(base + 8192 + b_d1, bh + (size_t)br1 * ldn + bc1 * 8);          \
} while (0)

    int mat = lane >> 3;
    int arb = wm * 64 + ((mat & 1) << 3) + (lane & 7);
    int asw = (arb >> 1) & 3;
    int bkb = ((mat & 1) << 3) + (lane & 7);
    int bsw = lane & 7;
    int bnc = wn * 4 + (mat >> 1);

    float acc[4][4][4];
#pragma unroll
    for (int i = 0; i < 4; i++)
#pragma unroll
        for (int j = 0; j < 4; j++)
#pragma unroll
            for (int q = 0; q < 4; q++) acc[i][j][q] = 0.f;

    LOAD_STAGE(0, 0);
    CP_COMMIT();
    if (nch > 1) {
        LOAD_STAGE(1, 1);
        CP_COMMIT();
    }

    int stg = 0;
    for (int ch = 0; ch < nch; ch++) {
        if (ch + 1 < nch) { CP_WAIT1(); } else { CP_WAIT0(); }
        __syncthreads();
        if (ch + 2 < nch) {
            int ns = stg + 2;
            if (ns >= 3) ns -= 3;
            LOAD_STAGE(ns, ch + 2);
            CP_COMMIT();
        }

        uint32_t Ab_hi = sb + (uint32_t)stg * 16384u;
        uint32_t Bb_hi = Ab_hi + 8192;

#pragma unroll
        for (int kh = 0; kh < 2; kh++) {
            uint32_t ac = (uint32_t)(((kh * 2 + (mat >> 1)) ^ asw) << 4);
            uint32_t a_hi[4][4];
#pragma unroll
            for (int mt = 0; mt < 4; mt++) {
                uint32_t ro = (uint32_t)((arb + mt * 16) * 64);
                ldsm_x4(a_hi[mt], Ab_hi + ro + ac);
            }
            uint32_t bro = (uint32_t)((kh * 16 + bkb) * 256);
            uint32_t b_hi[2][4];
#pragma unroll
            for (int p = 0; p < 2; p++) {
                uint32_t co = (uint32_t)((((bnc + p * 2)) ^ bsw) << 4);
                ldsm_x4t(b_hi[p], Bb_hi + bro + co);
            }
#pragma unroll
            for (int mt = 0; mt < 4; mt++)
#pragma unroll
                for (int p = 0; p < 2; p++) {
                    mma16816(acc[mt][p * 2],     a_hi[mt], b_hi[p][0], b_hi[p][1]);
                    mma16816(acc[mt][p * 2 + 1], a_hi[mt], b_hi[p][2], b_hi[p][3]);
                }
        }
        if (++stg == 3) stg = 0;
    }
#undef LOAD_STAGE

    if (FUSED && is_v) {
        // V epilogue: write truncated fp16 directly
#pragma unroll
        for (int mt = 0; mt < 4; mt++) {
            int row = bm * 128 + wm * 64 + mt * 16 + (lane >> 2);
#pragma unroll
            for (int nt = 0; nt < 4; nt++) {
                int col = bcol + wn * 32 + (nt >> 1) * 16 + (nt & 1) * 8 + (lane & 3) * 2;
                *(uint32_t*)(Vh + (size_t)row * ldn + col) =
                    pack_h2(acc[mt][nt][0], acc[mt][nt][1]);
                *(uint32_t*)(Vh + (size_t)(row + 8) * ldn + col) =
                    pack_h2(acc[mt][nt][2], acc[mt][nt][3]);
            }
        }
    } else {
#pragma unroll
        for (int mt = 0; mt < 4; mt++) {
            int row = bm * 128 + wm * 64 + mt * 16 + (lane >> 2);
#pragma unroll
            for (int nt = 0; nt < 4; nt++) {
                int col = bcol + wn * 32 + (nt >> 1) * 16 + (nt & 1) * 8 + (lane & 3) * 2;
                *(float2*)(C + (size_t)row * ldn + col) =
                    make_float2(acc[mt][nt][0], acc[mt][nt][1]);
                *(float2*)(C + (size_t)(row + 8) * ldn + col) =
                    make_float2(acc[mt][nt][2], acc[mt][nt][3]);
            }
        }
    }
}

// ---------------- HMMA flash attention: 3-term QK, 1-term PV ----------------
// smem: Q hi [0,32K) Q lo [32K,64K); stages at 65536 + stg*49152:
//   K hi [0,16K) K lo [16K,32K) V hi [32K,48K); sbias at 163840.
__global__ __launch_bounds__(256, 1)
void flash_hmma_kernel(const __half* __restrict__ Qhi, const __half* __restrict__ Qlo,
                       const __half* __restrict__ KhiT, const __half* __restrict__ KloT,
                       const __half* __restrict__ Vhi,
                       const int* __restrict__ amask,
                       __half* __restrict__ Ahi) {
    extern __shared__ char sm[];
    uint32_t sb = smem_u32(sm);
    float* sbias = (float*)(sm + 163840);

    int tid = threadIdx.x, wq = tid >> 5, lane = tid & 31;
    int mat = lane >> 3, l7 = lane & 7, qd = lane >> 2, l3 = lane & 3;
    int qb = (int)(gridDim.x - 1 - blockIdx.x);
    int h = blockIdx.y, kvh = h / REP;

    {
        const __half* qh = Qhi + ((size_t)(qb * 128) * NH + h) * HD;
        const __half* ql = Qlo + ((size_t)(qb * 128) * NH + h) * HD;
#pragma unroll
        for (int i = 0; i < 8; i++) {
            int idx = tid + i * 256;
            int row = idx >> 4, ch = idx & 15;
            uint32_t dst = sb + (uint32_t)(row * 256 + ((ch ^ (row & 7)) << 4));
            CPASYNC16(dst,         qh + (size_t)row * NHD + ch * 8);
            CPASYNC16(dst + 32768, ql + (size_t)row * NHD + ch * 8);
        }
    }

    auto load_kv = [&](int stage, int kb) {
        uint32_t base = sb + 65536u + (uint32_t)stage * 49152u;
        const __half* kh_ = KhiT + (size_t)kvh * HD * S_LEN + kb * 64;
        const __half* kl_ = KloT + (size_t)kvh * HD * S_LEN + kb * 64;
#pragma unroll
        for (int i = 0; i < 4; i++) {
            int idx = tid + i * 256;
            int row = idx >> 3, ch = idx & 7;
            uint32_t dst = base + (uint32_t)(row * 128 + ((ch ^ (row & 7)) << 4));
            CPASYNC16(dst,         kh_ + (size_t)row * S_LEN + ch * 8);
            CPASYNC16(dst + 16384, kl_ + (size_t)row * S_LEN + ch * 8);
        }
        const __half* vh_ = Vhi + ((size_t)(kb * 64) * NKV + kvh) * HD;
#pragma unroll
        for (int i = 0; i < 4; i++) {
            int idx = tid + i * 256;
            int row = idx >> 4, ch = idx & 15;
            uint32_t dst = base + 32768u + (uint32_t)(row * 256 + ((ch ^ (row & 7)) << 4));
            CPASYNC16(dst, vh_ + (size_t)row * NKV * HD + ch * 8);
        }
    };

    load_kv(0, 0);
    CP_COMMIT();

    float o[16][4];
#pragma unroll
    for (int i = 0; i < 16; i++)
#pragma unroll
        for (int j = 0; j < 4; j++) o[i][j] = 0.f;
    float m0 = -1e30f, m1 = -1e30f, l0 = 0.f, l1 = 0.f;

    int kbmax = 2 * qb + 1;
    int r0g = qb * 128 + wq * 16 + qd, r1g = r0g + 8;
    int arow = wq * 16 + ((mat & 1) << 3) + l7;
    int brow0 = ((mat & 1) << 3) + l7;

    for (int kb = 0; kb <= kbmax; kb++) {
        if (kb < kbmax) {
            load_kv((kb + 1) & 1, kb + 1);
            CP_COMMIT();
            CP_WAIT1();
        } else {
            CP_WAIT0();
        }
        if (tid < 64) sbias[tid] = amask[kb * 64 + tid] ? 0.f : -1e30f;
        __syncthreads();

        uint32_t Kb = sb + 65536u + (uint32_t)(kb & 1) * 49152u;
        uint32_t Vb = Kb + 32768u;

        float s[8][4];
#pragma unroll
        for (int i = 0; i < 8; i++)
#pragma unroll
            for (int j = 0; j < 4; j++) s[i][j] = 0.f;

#pragma unroll
        for (int kh2 = 0; kh2 < 8; kh2++) {
            uint32_t a_hi[4], a_lo[4];
            int ach = kh2 * 2 + (mat >> 1);
            uint32_t aaddr = sb + (uint32_t)(arow * 256 + ((ach ^ (arow & 7)) << 4));
            ldsm_x4(a_hi, aaddr);
            ldsm_x4(a_lo, aaddr + 32768);
            int brow = kh2 * 16 + brow0;
#pragma unroll
            for (int hf = 0; hf < 2; hf++) {
                uint32_t b_hi[2][4], b_lo[2][4];
#pragma unroll
                for (int p = 0; p < 2; p++) {
                    int bch = (hf * 2 + p) * 2 + (mat >> 1);
                    uint32_t baddr = Kb + (uint32_t)(brow * 128 + ((bch ^ (brow & 7)) << 4));
                    ldsm_x4t(b_hi[p], baddr);
                    ldsm_x4t(b_lo[p], baddr + 16384);
                }
#pragma unroll
                for (int p = 0; p < 2; p++)
#pragma unroll
                    for (int e = 0; e < 2; e++) {
                        int nt = hf * 4 + p * 2 + e;
                        mma16816(s[nt], a_hi, b_hi[p][e * 2], b_hi[p][e * 2 + 1]);
                        mma16816(s[nt], a_hi, b_lo[p][e * 2], b_lo[p][e * 2 + 1]);
                        mma16816(s[nt], a_lo, b_hi[p][e * 2], b_hi[p][e * 2 + 1]);
                    }
            }
        }

#pragma unroll
        for (int nt = 0; nt < 8; nt++) {
            int c = nt * 8 + 2 * l3;
            float b0 = sbias[c], b1 = sbias[c + 1];
            s[nt][0] += b0; s[nt][1] += b1; s[nt][2] += b0; s[nt][3] += b1;
        }
        if (kb >= 2 * qb) {
            int cbase = kb * 64 + 2 * l3;
#pragma unroll
            for (int nt = 0; nt < 8; nt++) {
                int c0 = cbase + nt * 8, c1 = c0 + 1;
                if (c0 > r0g) s[nt][0] = -1e30f;
                if (c1 > r0g) s[nt][1] = -1e30f;
                if (c0 > r1g) s[nt][2] = -1e30f;
                if (c1 > r1g) s[nt][3] = -1e30f;
            }
        }

        float mx0 = -1e30f, mx1 = -1e30f;
#pragma unroll
        for (int nt = 0; nt < 8; nt++) {
            mx0 = fmaxf(mx0, fmaxf(s[nt][0], s[nt][1]));
            mx1 = fmaxf(mx1, fmaxf(s[nt][2], s[nt][3]));
        }
        mx0 = fmaxf(mx0, __shfl_xor_sync(0xffffffffu, mx0, 1));
        mx0 = fmaxf(mx0, __shfl_xor_sync(0xffffffffu, mx0, 2));
        mx1 = fmaxf(mx1, __shfl_xor_sync(0xffffffffu, mx1, 1));
        mx1 = fmaxf(mx1, __shfl_xor_sync(0xffffffffu, mx1, 2));
        float mn0 = fmaxf(m0, mx0), mn1 = fmaxf(m1, mx1);
        float al0 = __expf(m0 - mn0), al1 = __expf(m1 - mn1);
        m0 = mn0; m1 = mn1;
        float rs0 = 0.f, rs1 = 0.f;
#pragma unroll
        for (int nt = 0; nt < 8; nt++) {
            s[nt][0] = __expf(s[nt][0] - mn0); rs0 += s[nt][0];
            s[nt][1] = __expf(s[nt][1] - mn0); rs0 += s[nt][1];
            s[nt][2] = __expf(s[nt][2] - mn1); rs1 += s[nt][2];
            s[nt][3] = __expf(s[nt][3] - mn1); rs1 += s[nt][3];
        }
        rs0 += __shfl_xor_sync(0xffffffffu, rs0, 1);
        rs0 += __shfl_xor_sync(0xffffffffu, rs0, 2);
        rs1 += __shfl_xor_sync(0xffffffffu, rs1, 1);
        rs1 += __shfl_xor_sync(0xffffffffu, rs1, 2);
        l0 = l0 * al0 + rs0;
        l1 = l1 * al1 + rs1;
#pragma unroll
        for (int nt = 0; nt < 16; nt++) {
            o[nt][0] *= al0; o[nt][1] *= al0;
            o[nt][2] *= al1; o[nt][3] *= al1;
        }

        // ---- O += P V (1-term: V residual dropped)
#pragma unroll
        for (int j = 0; j < 4; j++) {
            uint32_t phi[4];
            phi[0] = pack_h2(s[2 * j][0],     s[2 * j][1]);
            phi[1] = pack_h2(s[2 * j][2],     s[2 * j][3]);
            phi[2] = pack_h2(s[2 * j + 1][0], s[2 * j + 1][1]);
            phi[3] = pack_h2(s[2 * j + 1][2], s[2 * j + 1][3]);
            int vrow = j * 16 + ((mat & 1) << 3) + l7;
#pragma unroll
            for (int nb = 0; nb < 8; nb++) {
                uint32_t v_hi[4];
                int vch = nb * 2 + (mat >> 1);
                uint32_t vaddr = Vb + (uint32_t)(vrow * 256 + ((vch ^ (vrow & 7)) << 4));
                ldsm_x4t(v_hi, vaddr);
#pragma unroll
                for (int e = 0; e < 2; e++) {
                    int nt = nb * 2 + e;
                    mma16816(o[nt], phi, v_hi[e * 2], v_hi[e * 2 + 1]);
                }
            }
        }
        __syncthreads();
    }

    float inv0 = 1.f / l0, inv1 = 1.f / l1;
    size_t ro0 = (size_t)r0g * NHD + h * HD + 2 * l3;
    size_t ro1 = (size_t)r1g * NHD + h * HD + 2 * l3;
#pragma unroll
    for (int nt = 0; nt < 16; nt++) {
        *(uint32_t*)(Ahi + ro0 + nt * 8) = pack_h2(o[nt][0] * inv0, o[nt][1] * inv0);
        *(uint32_t*)(Ahi + ro1 + nt * 8) = pack_h2(o[nt][2] * inv1, o[nt][3] * inv1);
    }
}

// ---------------- launcher ---------------------------------------------------
extern "C" void kernel_launch(void* const* d_in, const int* in_sizes, int n_in,
                              void* d_out, int out_size) {
    const float* x     = (const float*)d_in[0];
    const int*   amask = (const int*)  d_in[1];
    const int*   pos   = (const int*)  d_in[2];
    const float* Wq    = (const float*)d_in[3];
    const float* Wk    = (const float*)d_in[4];
    const float* Wv    = (const float*)d_in[5];
    const float* Wo    = (const float*)d_in[6];
    float* out = (float*)d_out;

    float *qp, *kp;
    cudaGetSymbolAddress((void**)&qp, g_q);
    cudaGetSymbolAddress((void**)&kp, g_k);
    __half *xh, *wqh, *wkh, *wvh, *woh, *ah;
    __half *qhi, *qlo, *khiT, *kloT, *vhi;
    cudaGetSymbolAddress((void**)&xh,  g_x_hi);
    cudaGetSymbolAddress((void**)&wqh, g_wq_hi);
    cudaGetSymbolAddress((void**)&wkh, g_wk_hi);
    cudaGetSymbolAddress((void**)&wvh, g_wv_hi);
    cudaGetSymbolAddress((void**)&woh, g_wo_hi);
    cudaGetSymbolAddress((void**)&ah,  g_a_hi);
    cudaGetSymbolAddress((void**)&qhi, g_qhi);   cudaGetSymbolAddress((void**)&qlo, g_qlo);
    cudaGetSymbolAddress((void**)&khiT, g_khiT); cudaGetSymbolAddress((void**)&kloT, g_kloT);
    cudaGetSymbolAddress((void**)&vhi, g_vhi);

    // 0) fused fp16 truncation of x + all weights + RoPE table
    const int SPLIT_TOT = (S_LEN * HID + HID * NH * HD + 2 * HID * NKV * HD
                           + NH * HD * HID) / 4 + S_LEN * 64;
    split_all_kernel<<<(SPLIT_TOT + 255) / 256, 256>>>(
        x, Wq, Wk, Wv, Wo, pos, xh, wqh, wkh, wvh, woh);

    // 1) fused QKV projection (HMMA, pure fp16; V truncated in-epilogue)
    const int gemm_smem = 49152;
    cudaFuncSetAttribute(gemm_hmma_kernel<1>,
                         cudaFuncAttributeMaxDynamicSharedMemorySize, gemm_smem);
    cudaFuncSetAttribute(gemm_hmma_kernel<0>,
                         cudaFuncAttributeMaxDynamicSharedMemorySize, gemm_smem);
    gemm_hmma_kernel<1><<<dim3(36, 16), 256, gemm_smem>>>(
        xh, wqh, wkh, wvh, qp, kp, vhi, HID, NH * HD);

    // 2) fused RoPE+split (Q, K^T)
    const int PREP_TOT = S_LEN * NH * 64 + S_LEN * NKV * 64;
    prep_attention_kernel<<<(PREP_TOT + 255) / 256, 256>>>(
        qp, kp, qhi, qlo, khiT, kloT);

    // 3) HMMA flash attention (3-term QK, 1-term PV) -> fp16 hi output
    const int flash_smem = 164096;
    cudaFuncSetAttribute(flash_hmma_kernel,
                         cudaFuncAttributeMaxDynamicSharedMemorySize, flash_smem);
    flash_hmma_kernel<<<dim3(S_LEN / 128, NH), 256, flash_smem>>>(
        qhi, qlo, khiT, kloT, vhi, amask, ah);

    // 4) O projection (HMMA, pure fp16) -> final output
    gemm_hmma_kernel<0><<<dim3(28, 16), 256, gemm_smem>>>(
        ah, woh, nullptr, nullptr, out, nullptr, nullptr, HID, HID);
}